// round 1
// baseline (speedup 1.0000x reference)
#include <cuda_runtime.h>
#include <math.h>
#include <stdint.h>

// Problem constants (fixed shapes from reference)
#define SEQ   2048
#define HID   2048
#define NHEAD 16
#define HDIM  128
#define QKV_N (3 * HID)   // 6144
#define MASK_VAL (-10000.0f)

// -------- device scratch (static; no allocations allowed) --------
__device__ float g_qkv[SEQ * QKV_N];                    // [s, 3h] fused QKV output (~50 MB)
__device__ float g_scores[(size_t)NHEAD * SEQ * SEQ];   // [n, s, t] scores -> probs (~268 MB)
__device__ float g_ctx[SEQ * HID];                      // [s, h] merged context (~17 MB)

// ============================================================================
// Generic 128x128 tiled fp32 GEMM:  C = alpha * A * op(B) + bias
//   A: [M, K] row-major, row stride lda, batch stride aBS
//   B_TRANS=true  : B is [N, K] row-major (C = A * B^T)
//   B_TRANS=false : B is [K, N] row-major (C = A * B)
//   C: [M, N] row stride ldc, batch stride cBS
// Assumes M, N multiples of 128 per batch, K multiple of 8, pointers 16B-aligned.
// causal=1: skip tiles entirely above the diagonal (tile col > tile row).
// ============================================================================
template<bool B_TRANS>
__global__ void __launch_bounds__(256, 2)
gemm_tile(const float* __restrict__ A, int lda, long aBS,
          const float* __restrict__ B, int ldb, long bBS,
          float* __restrict__ C, int ldc, long cBS,
          const float* __restrict__ bias,
          int K, float alpha, int causal)
{
    if (causal && (int)blockIdx.x > (int)blockIdx.y) return;

    __shared__ float As[8][128];
    __shared__ float Bs[8][128];

    const int tid = threadIdx.x;
    const int tx  = tid & 15;        // 0..15  -> 8 cols each
    const int ty  = tid >> 4;        // 0..15  -> 8 rows each

    // global load addressing
    const int arow = tid >> 1;            // 0..127
    const int acol = (tid & 1) * 4;       // 0 or 4
    const float* a_ptr = A + (size_t)blockIdx.z * aBS
                           + (size_t)(blockIdx.y * 128 + arow) * lda + acol;

    const float* b_ptr;
    if (B_TRANS) {
        // B[N, K]: same pattern as A but over cols
        b_ptr = B + (size_t)blockIdx.z * bBS
                  + (size_t)(blockIdx.x * 128 + arow) * ldb + acol;
    } else {
        // B[K, N]: 8 k-rows x 128 n-cols per tile
        const int bk = tid >> 5;          // 0..7
        const int bn = (tid & 31) * 4;    // 0..124
        b_ptr = B + (size_t)blockIdx.z * bBS
                  + (size_t)bk * ldb + blockIdx.x * 128 + bn;
    }

    float acc[8][8];
    #pragma unroll
    for (int i = 0; i < 8; i++)
        #pragma unroll
        for (int j = 0; j < 8; j++) acc[i][j] = 0.0f;

    for (int k0 = 0; k0 < K; k0 += 8) {
        float4 av = *(const float4*)a_ptr;
        float4 bv = *(const float4*)b_ptr;

        __syncthreads();   // prior compute done reading smem

        As[acol + 0][arow] = av.x;
        As[acol + 1][arow] = av.y;
        As[acol + 2][arow] = av.z;
        As[acol + 3][arow] = av.w;
        if (B_TRANS) {
            Bs[acol + 0][arow] = bv.x;
            Bs[acol + 1][arow] = bv.y;
            Bs[acol + 2][arow] = bv.z;
            Bs[acol + 3][arow] = bv.w;
        } else {
            *(float4*)&Bs[tid >> 5][(tid & 31) * 4] = bv;
        }

        __syncthreads();

        #pragma unroll
        for (int kk = 0; kk < 8; kk++) {
            float a[8], b[8];
            *(float4*)&a[0] = *(const float4*)&As[kk][ty * 8];
            *(float4*)&a[4] = *(const float4*)&As[kk][ty * 8 + 4];
            *(float4*)&b[0] = *(const float4*)&Bs[kk][tx * 8];
            *(float4*)&b[4] = *(const float4*)&Bs[kk][tx * 8 + 4];
            #pragma unroll
            for (int i = 0; i < 8; i++)
                #pragma unroll
                for (int j = 0; j < 8; j++)
                    acc[i][j] = fmaf(a[i], b[j], acc[i][j]);
        }

        a_ptr += 8;
        if (B_TRANS) b_ptr += 8;
        else         b_ptr += (size_t)8 * ldb;
    }

    // epilogue
    const int row0 = blockIdx.y * 128 + ty * 8;
    const int col0 = blockIdx.x * 128 + tx * 8;
    float bvals[8];
    #pragma unroll
    for (int j = 0; j < 8; j++)
        bvals[j] = (bias != nullptr) ? bias[col0 + j] : 0.0f;

    float* c = C + (size_t)blockIdx.z * cBS;
    #pragma unroll
    for (int i = 0; i < 8; i++) {
        float4 v0, v1;
        v0.x = acc[i][0] * alpha + bvals[0];
        v0.y = acc[i][1] * alpha + bvals[1];
        v0.z = acc[i][2] * alpha + bvals[2];
        v0.w = acc[i][3] * alpha + bvals[3];
        v1.x = acc[i][4] * alpha + bvals[4];
        v1.y = acc[i][5] * alpha + bvals[5];
        v1.z = acc[i][6] * alpha + bvals[6];
        v1.w = acc[i][7] * alpha + bvals[7];
        *(float4*)&c[(size_t)(row0 + i) * ldc + col0]     = v0;
        *(float4*)&c[(size_t)(row0 + i) * ldc + col0 + 4] = v1;
    }
}

// ============================================================================
// Row softmax with causal + user mask. One block per (s, head) row.
// Reads scores[n][s][0..s], applies mask bytes, writes probs, zeros t>s.
// ============================================================================
__global__ void __launch_bounds__(256)
softmax_causal(const uint8_t* __restrict__ mask)
{
    const int s = blockIdx.x;
    const int n = blockIdx.y;
    float* row = g_scores + ((size_t)n * SEQ + s) * SEQ;
    const uint8_t* mrow = mask + (size_t)s * SEQ;
    const int valid = s + 1;
    const int tid = threadIdx.x;

    __shared__ float buf[SEQ];
    __shared__ float red[256];

    // load + mask
    float m = -1e30f;
    for (int t = tid; t < valid; t += 256) {
        float v = mrow[t] ? MASK_VAL : row[t];
        buf[t] = v;
        m = fmaxf(m, v);
    }
    red[tid] = m;
    __syncthreads();
    #pragma unroll
    for (int o = 128; o > 0; o >>= 1) {
        if (tid < o) red[tid] = fmaxf(red[tid], red[tid + o]);
        __syncthreads();
    }
    m = red[0];
    __syncthreads();

    float sum = 0.0f;
    for (int t = tid; t < valid; t += 256) {
        float e = expf(buf[t] - m);
        buf[t] = e;
        sum += e;
    }
    red[tid] = sum;
    __syncthreads();
    #pragma unroll
    for (int o = 128; o > 0; o >>= 1) {
        if (tid < o) red[tid] += red[tid + o];
        __syncthreads();
    }
    const float inv = 1.0f / red[0];
    __syncthreads();

    for (int t = tid; t < valid; t += 256) row[t] = buf[t] * inv;
    for (int t = valid + tid; t < SEQ; t += 256) row[t] = 0.0f;
}

__global__ void copy_bias(const float* __restrict__ b, float* __restrict__ out)
{
    int i = blockIdx.x * 256 + threadIdx.x;
    if (i < HID) out[i] = b[i];
}

// ============================================================================
extern "C" void kernel_launch(void* const* d_in, const int* in_sizes, int n_in,
                              void* d_out, int out_size)
{
    const float*   hs     = (const float*)d_in[0];   // [2048, 1, 2048]
    const float*   w_qkv  = (const float*)d_in[1];   // [6144, 2048]
    const float*   b_qkv  = (const float*)d_in[2];   // [6144]
    const float*   w_proj = (const float*)d_in[3];   // [2048, 2048]
    const float*   b_proj = (const float*)d_in[4];   // [2048]
    const uint8_t* mask   = (const uint8_t*)d_in[5]; // [1,1,2048,2048] bool

    float* qkv;    cudaGetSymbolAddress((void**)&qkv,    g_qkv);
    float* scores; cudaGetSymbolAddress((void**)&scores, g_scores);
    float* ctx;    cudaGetSymbolAddress((void**)&ctx,    g_ctx);
    float* out = (float*)d_out;

    const float inv_norm = 1.0f / sqrtf((float)HDIM);

    // 1) fused QKV GEMM: qkv[s,o] = hs[s,:] . w_qkv[o,:] + b_qkv[o]
    gemm_tile<true><<<dim3(QKV_N / 128, SEQ / 128, 1), 256>>>(
        hs,    HID,   0,
        w_qkv, HID,   0,
        qkv,   QKV_N, 0,
        b_qkv, HID, 1.0f, 0);

    // 2) BMM1 (per head): scores[n][s][t] = q[s,n,:].k[t,n,:] / sqrt(HN)
    //    q rows at qkv + n*384, k rows at qkv + n*384 + 128. Causal tile skip.
    gemm_tile<true><<<dim3(SEQ / 128, SEQ / 128, NHEAD), 256>>>(
        qkv,        QKV_N, 3 * HDIM,
        qkv + HDIM, QKV_N, 3 * HDIM,
        scores,     SEQ,   (long)SEQ * SEQ,
        nullptr, HDIM, inv_norm, 1);

    // 3) causal softmax (fp32), zeros above diagonal
    softmax_causal<<<dim3(SEQ, NHEAD), 256>>>(mask);

    // 4) BMM2 (per head): ctx[s, n*128+d] = sum_t probs[n][s][t] * v[t,n,d]
    gemm_tile<false><<<dim3(1, SEQ / 128, NHEAD), 256>>>(
        scores,         SEQ,   (long)SEQ * SEQ,
        qkv + 2 * HDIM, QKV_N, 3 * HDIM,
        ctx,            HID,   HDIM,
        nullptr, SEQ, 1.0f, 0);

    // 5) output projection (bias returned separately): out[s,o] = ctx[s,:].w_proj[o,:]
    gemm_tile<true><<<dim3(HID / 128, SEQ / 128, 1), 256>>>(
        ctx,    HID, 0,
        w_proj, HID, 0,
        out,    HID, 0,
        nullptr, HID, 1.0f, 0);

    // 6) tuple second element: b_proj appended after the [S*H] projection output
    if (out_size >= SEQ * HID + HID) {
        copy_bias<<<(HID + 255) / 256, 256>>>(b_proj, out + (size_t)SEQ * HID);
    }
}

// round 3
// speedup vs baseline: 1.9900x; 1.9900x over previous
#include <cuda_runtime.h>
#include <math.h>
#include <stdint.h>

// Problem constants (fixed shapes from reference)
#define SEQ   2048
#define HID   2048
#define NHEAD 16
#define HDIM  128
#define QKV_N (3 * HID)   // 6144
#define MASK_VAL (-10000.0f)

// -------- device scratch (static; no allocations allowed) --------
__device__ float g_qkv[SEQ * QKV_N];                    // [s, 3h] fused QKV output
__device__ float g_scores[(size_t)NHEAD * SEQ * SEQ];   // [n, s, t] scores -> probs
__device__ float g_ctx[SEQ * HID];                      // [s, h] merged context

// ---------------------------------------------------------------------------
// tf32 helpers (baseline PTX, works on compute_103 target)
// ---------------------------------------------------------------------------
__device__ __forceinline__ uint32_t f2tf32(float f) {
    uint32_t u;
    asm("cvt.rna.tf32.f32 %0, %1;" : "=r"(u) : "f"(f));
    return u;
}

__device__ __forceinline__ void mma_tf32(float* d, const uint32_t* a, const uint32_t* b) {
    asm volatile(
        "mma.sync.aligned.m16n8k8.row.col.f32.tf32.tf32.f32 "
        "{%0,%1,%2,%3}, {%4,%5,%6,%7}, {%8,%9}, {%0,%1,%2,%3};"
        : "+f"(d[0]), "+f"(d[1]), "+f"(d[2]), "+f"(d[3])
        : "r"(a[0]), "r"(a[1]), "r"(a[2]), "r"(a[3]), "r"(b[0]), "r"(b[1]));
}

// ---------------------------------------------------------------------------
// tf32 mma.sync GEMM: C = alpha * A * op(B) + bias
//   CTA tile 128x128, BK=16, 256 threads = 8 warps (2 M x 4 N), warp tile 64x32.
//   B_TRANS=true : B[N,K] row-major (C = A*B^T)
//   B_TRANS=false: B[K,N] row-major (C = A*B)
//   causal=1: skip tiles strictly above the diagonal.
// SMEM: [128][20] padded rows -> conflict-free fragment loads.
// ---------------------------------------------------------------------------
#define SMS 20   // smem row stride (floats): 16 + 4 pad

template<bool B_TRANS>
__global__ void __launch_bounds__(256)
gemm_mma(const float* __restrict__ A, int lda, long aBS,
         const float* __restrict__ B, int ldb, long bBS,
         float* __restrict__ C, int ldc, long cBS,
         const float* __restrict__ bias,
         int K, float alpha, int causal)
{
    if (causal && (int)blockIdx.x > (int)blockIdx.y) return;

    __shared__ float As[2][128 * SMS];
    __shared__ float Bs[2][128 * SMS];

    const int tid = threadIdx.x;
    const int wid = tid >> 5;
    const int lane = tid & 31;
    const int g = lane >> 2;        // groupID 0..7
    const int t = lane & 3;         // thread-in-group 0..3
    const int wm = wid & 1;         // warp row (0..1) -> 64 rows each
    const int wn = wid >> 1;        // warp col (0..3) -> 32 cols each

    A += (size_t)blockIdx.z * aBS + (size_t)(blockIdx.y * 128) * lda;
    if (B_TRANS) B += (size_t)blockIdx.z * bBS + (size_t)(blockIdx.x * 128) * ldb;
    else         B += (size_t)blockIdx.z * bBS + blockIdx.x * 128;

    // global-load addressing (row-major tiles): 512 float4 groups / 256 thr = 2 each
    const int lr = tid >> 2;        // row 0..63  (i adds 64)
    const int lc = tid & 3;         // float4 group 0..3
    // non-trans B gather addressing
    const int bn = tid & 127;       // n within tile
    const int bkh = (tid >> 7) * 8; // k half: 0 or 8

    float acc[4][4][4];
    #pragma unroll
    for (int mi = 0; mi < 4; mi++)
        #pragma unroll
        for (int ni = 0; ni < 4; ni++)
            #pragma unroll
            for (int q = 0; q < 4; q++) acc[mi][ni][q] = 0.0f;

    const int nch = K >> 4;   // K / 16

    // ---- load chunk 0 into stage 0 ----
    {
        #pragma unroll
        for (int i = 0; i < 2; i++) {
            int r = lr + i * 64;
            float4 av = *(const float4*)(A + (size_t)r * lda + lc * 4);
            float* d = &As[0][r * SMS + lc * 4];
            d[0] = __uint_as_float(f2tf32(av.x));
            d[1] = __uint_as_float(f2tf32(av.y));
            d[2] = __uint_as_float(f2tf32(av.z));
            d[3] = __uint_as_float(f2tf32(av.w));
        }
        if (B_TRANS) {
            #pragma unroll
            for (int i = 0; i < 2; i++) {
                int r = lr + i * 64;
                float4 bv = *(const float4*)(B + (size_t)r * ldb + lc * 4);
                float* d = &Bs[0][r * SMS + lc * 4];
                d[0] = __uint_as_float(f2tf32(bv.x));
                d[1] = __uint_as_float(f2tf32(bv.y));
                d[2] = __uint_as_float(f2tf32(bv.z));
                d[3] = __uint_as_float(f2tf32(bv.w));
            }
        } else {
            #pragma unroll
            for (int j = 0; j < 8; j++) {
                float v = B[(size_t)(bkh + j) * ldb + bn];
                Bs[0][bn * SMS + bkh + j] = __uint_as_float(f2tf32(v));
            }
        }
    }
    __syncthreads();

    float4 a_next[2], b_next[2];
    float  bs_next[8];

    for (int c = 0; c < nch; c++) {
        const int cur = c & 1;
        const int nxt = cur ^ 1;
        const bool has_next = (c + 1 < nch);

        // ---- prefetch next chunk into registers ----
        if (has_next) {
            int k0 = (c + 1) * 16;
            #pragma unroll
            for (int i = 0; i < 2; i++) {
                int r = lr + i * 64;
                a_next[i] = *(const float4*)(A + (size_t)r * lda + k0 + lc * 4);
            }
            if (B_TRANS) {
                #pragma unroll
                for (int i = 0; i < 2; i++) {
                    int r = lr + i * 64;
                    b_next[i] = *(const float4*)(B + (size_t)r * ldb + k0 + lc * 4);
                }
            } else {
                #pragma unroll
                for (int j = 0; j < 8; j++)
                    bs_next[j] = B[(size_t)(k0 + bkh + j) * ldb + bn];
            }
        }

        // ---- compute current chunk: 2 k-steps of k=8 ----
        const float* as = As[cur];
        const float* bs = Bs[cur];
        #pragma unroll
        for (int ks = 0; ks < 2; ks++) {
            const int k = ks * 8;
            uint32_t af[4][4], bf[4][2];
            #pragma unroll
            for (int mi = 0; mi < 4; mi++) {
                int rm = wm * 64 + mi * 16 + g;
                af[mi][0] = __float_as_uint(as[rm * SMS + k + t]);
                af[mi][1] = __float_as_uint(as[(rm + 8) * SMS + k + t]);
                af[mi][2] = __float_as_uint(as[rm * SMS + k + t + 4]);
                af[mi][3] = __float_as_uint(as[(rm + 8) * SMS + k + t + 4]);
            }
            #pragma unroll
            for (int ni = 0; ni < 4; ni++) {
                int cn = wn * 32 + ni * 8 + g;
                bf[ni][0] = __float_as_uint(bs[cn * SMS + k + t]);
                bf[ni][1] = __float_as_uint(bs[cn * SMS + k + t + 4]);
            }
            #pragma unroll
            for (int mi = 0; mi < 4; mi++)
                #pragma unroll
                for (int ni = 0; ni < 4; ni++)
                    mma_tf32(acc[mi][ni], af[mi], bf[ni]);
        }

        // ---- store prefetched regs into next stage ----
        if (has_next) {
            #pragma unroll
            for (int i = 0; i < 2; i++) {
                int r = lr + i * 64;
                float* d = &As[nxt][r * SMS + lc * 4];
                d[0] = __uint_as_float(f2tf32(a_next[i].x));
                d[1] = __uint_as_float(f2tf32(a_next[i].y));
                d[2] = __uint_as_float(f2tf32(a_next[i].z));
                d[3] = __uint_as_float(f2tf32(a_next[i].w));
            }
            if (B_TRANS) {
                #pragma unroll
                for (int i = 0; i < 2; i++) {
                    int r = lr + i * 64;
                    float* d = &Bs[nxt][r * SMS + lc * 4];
                    d[0] = __uint_as_float(f2tf32(b_next[i].x));
                    d[1] = __uint_as_float(f2tf32(b_next[i].y));
                    d[2] = __uint_as_float(f2tf32(b_next[i].z));
                    d[3] = __uint_as_float(f2tf32(b_next[i].w));
                }
            } else {
                #pragma unroll
                for (int j = 0; j < 8; j++)
                    Bs[nxt][bn * SMS + bkh + j] = __uint_as_float(f2tf32(bs_next[j]));
            }
            __syncthreads();
        }
    }

    // ---- epilogue ----
    float* c0 = C + (size_t)blockIdx.z * cBS;
    #pragma unroll
    for (int mi = 0; mi < 4; mi++) {
        const int r0 = blockIdx.y * 128 + wm * 64 + mi * 16 + g;
        #pragma unroll
        for (int ni = 0; ni < 4; ni++) {
            const int col = blockIdx.x * 128 + wn * 32 + ni * 8 + t * 2;
            float bv0 = 0.0f, bv1 = 0.0f;
            if (bias != nullptr) { bv0 = bias[col]; bv1 = bias[col + 1]; }
            float2 v0, v1;
            v0.x = acc[mi][ni][0] * alpha + bv0;
            v0.y = acc[mi][ni][1] * alpha + bv1;
            v1.x = acc[mi][ni][2] * alpha + bv0;
            v1.y = acc[mi][ni][3] * alpha + bv1;
            *(float2*)(c0 + (size_t)r0 * ldc + col)       = v0;
            *(float2*)(c0 + (size_t)(r0 + 8) * ldc + col) = v1;
        }
    }
}

// ============================================================================
// Row softmax with causal + user mask. One block per (s, head) row.
// ============================================================================
__global__ void __launch_bounds__(256)
softmax_causal(const uint8_t* __restrict__ mask)
{
    const int s = blockIdx.x;
    const int n = blockIdx.y;
    float* row = g_scores + ((size_t)n * SEQ + s) * SEQ;
    const uint8_t* mrow = mask + (size_t)s * SEQ;
    const int valid = s + 1;
    const int tid = threadIdx.x;

    __shared__ float buf[SEQ];
    __shared__ float red[256];

    float m = -1e30f;
    for (int t = tid; t < valid; t += 256) {
        float v = mrow[t] ? MASK_VAL : row[t];
        buf[t] = v;
        m = fmaxf(m, v);
    }
    red[tid] = m;
    __syncthreads();
    #pragma unroll
    for (int o = 128; o > 0; o >>= 1) {
        if (tid < o) red[tid] = fmaxf(red[tid], red[tid + o]);
        __syncthreads();
    }
    m = red[0];
    __syncthreads();

    float sum = 0.0f;
    for (int t = tid; t < valid; t += 256) {
        float e = expf(buf[t] - m);
        buf[t] = e;
        sum += e;
    }
    red[tid] = sum;
    __syncthreads();
    #pragma unroll
    for (int o = 128; o > 0; o >>= 1) {
        if (tid < o) red[tid] += red[tid + o];
        __syncthreads();
    }
    const float inv = 1.0f / red[0];
    __syncthreads();

    for (int t = tid; t < valid; t += 256) row[t] = buf[t] * inv;
    for (int t = valid + tid; t < SEQ; t += 256) row[t] = 0.0f;
}

__global__ void copy_bias(const float* __restrict__ b, float* __restrict__ out)
{
    int i = blockIdx.x * 256 + threadIdx.x;
    if (i < HID) out[i] = b[i];
}

// ============================================================================
extern "C" void kernel_launch(void* const* d_in, const int* in_sizes, int n_in,
                              void* d_out, int out_size)
{
    const float*   hs     = (const float*)d_in[0];   // [2048, 1, 2048]
    const float*   w_qkv  = (const float*)d_in[1];   // [6144, 2048]
    const float*   b_qkv  = (const float*)d_in[2];   // [6144]
    const float*   w_proj = (const float*)d_in[3];   // [2048, 2048]
    const float*   b_proj = (const float*)d_in[4];   // [2048]
    const uint8_t* mask   = (const uint8_t*)d_in[5]; // [1,1,2048,2048] bool

    float* qkv;    cudaGetSymbolAddress((void**)&qkv,    g_qkv);
    float* scores; cudaGetSymbolAddress((void**)&scores, g_scores);
    float* ctx;    cudaGetSymbolAddress((void**)&ctx,    g_ctx);
    float* out = (float*)d_out;

    const float inv_norm = 1.0f / sqrtf((float)HDIM);

    // 1) fused QKV GEMM: qkv[s,o] = hs[s,:] . w_qkv[o,:] + b_qkv[o]
    gemm_mma<true><<<dim3(QKV_N / 128, SEQ / 128, 1), 256>>>(
        hs,    HID,   0,
        w_qkv, HID,   0,
        qkv,   QKV_N, 0,
        b_qkv, HID, 1.0f, 0);

    // 2) BMM1 (per head): scores[n][s][t] = q[s,n,:].k[t,n,:] / sqrt(HN), causal skip
    gemm_mma<true><<<dim3(SEQ / 128, SEQ / 128, NHEAD), 256>>>(
        qkv,        QKV_N, 3 * HDIM,
        qkv + HDIM, QKV_N, 3 * HDIM,
        scores,     SEQ,   (long)SEQ * SEQ,
        nullptr, HDIM, inv_norm, 1);

    // 3) causal softmax (fp32), zeros above diagonal
    softmax_causal<<<dim3(SEQ, NHEAD), 256>>>(mask);

    // 4) BMM2 (per head): ctx[s, n*128+d] = sum_t probs[n][s][t] * v[t,n,d]
    gemm_mma<false><<<dim3(1, SEQ / 128, NHEAD), 256>>>(
        scores,         SEQ,   (long)SEQ * SEQ,
        qkv + 2 * HDIM, QKV_N, 3 * HDIM,
        ctx,            HID,   HDIM,
        nullptr, SEQ, 1.0f, 0);

    // 5) output projection (bias returned separately)
    gemm_mma<true><<<dim3(HID / 128, SEQ / 128, 1), 256>>>(
        ctx,    HID, 0,
        w_proj, HID, 0,
        out,    HID, 0,
        nullptr, HID, 1.0f, 0);

    // 6) tuple second element: b_proj appended after the [S*H] projection output
    if (out_size >= SEQ * HID + HID) {
        copy_bias<<<(HID + 255) / 256, 256>>>(b_proj, out + (size_t)SEQ * HID);
    }
}

// round 4
// speedup vs baseline: 3.3305x; 1.6736x over previous
#include <cuda_runtime.h>
#include <math.h>
#include <stdint.h>

// Problem constants (fixed shapes from reference)
#define SEQ   2048
#define HID   2048
#define NHEAD 16
#define HDIM  128
#define QKV_N (3 * HID)   // 6144
#define MASK_VAL (-10000.0f)

// -------- device scratch (static; no allocations allowed) --------
__device__ float g_qkv[SEQ * QKV_N];   // [s, 3h] fused QKV output
__device__ float g_ctx[SEQ * HID];     // [s, h] merged context

// ---------------------------------------------------------------------------
// tf32 helpers (baseline PTX, works on compute_103 target)
// ---------------------------------------------------------------------------
__device__ __forceinline__ uint32_t f2tf32(float f) {
    uint32_t u;
    asm("cvt.rna.tf32.f32 %0, %1;" : "=r"(u) : "f"(f));
    return u;
}

__device__ __forceinline__ void mma_tf32(float* d, const uint32_t* a, const uint32_t* b) {
    asm volatile(
        "mma.sync.aligned.m16n8k8.row.col.f32.tf32.tf32.f32 "
        "{%0,%1,%2,%3}, {%4,%5,%6,%7}, {%8,%9}, {%0,%1,%2,%3};"
        : "+f"(d[0]), "+f"(d[1]), "+f"(d[2]), "+f"(d[3])
        : "r"(a[0]), "r"(a[1]), "r"(a[2]), "r"(a[3]), "r"(b[0]), "r"(b[1]));
}

// ---------------------------------------------------------------------------
// tf32 mma.sync GEMM (for QKV + proj): C = alpha * A * B^T + bias
//   CTA tile 128x128, BK=16, 256 threads = 8 warps (2 M x 4 N), warp tile 64x32.
// ---------------------------------------------------------------------------
#define SMS 20   // smem row stride (floats): 16 + 4 pad

__global__ void __launch_bounds__(256)
gemm_mma(const float* __restrict__ A, int lda,
         const float* __restrict__ B, int ldb,
         float* __restrict__ C, int ldc,
         const float* __restrict__ bias, int K)
{
    __shared__ float As[2][128 * SMS];
    __shared__ float Bs[2][128 * SMS];

    const int tid = threadIdx.x;
    const int wid = tid >> 5;
    const int lane = tid & 31;
    const int g = lane >> 2;
    const int t = lane & 3;
    const int wm = wid & 1;
    const int wn = wid >> 1;

    A += (size_t)(blockIdx.y * 128) * lda;
    B += (size_t)(blockIdx.x * 128) * ldb;

    const int lr = tid >> 2;
    const int lc = tid & 3;

    float acc[4][4][4];
    #pragma unroll
    for (int mi = 0; mi < 4; mi++)
        #pragma unroll
        for (int ni = 0; ni < 4; ni++)
            #pragma unroll
            for (int q = 0; q < 4; q++) acc[mi][ni][q] = 0.0f;

    const int nch = K >> 4;

    // chunk 0 -> stage 0
    #pragma unroll
    for (int i = 0; i < 2; i++) {
        int r = lr + i * 64;
        float4 av = *(const float4*)(A + (size_t)r * lda + lc * 4);
        float4 bv = *(const float4*)(B + (size_t)r * ldb + lc * 4);
        float* da = &As[0][r * SMS + lc * 4];
        float* db = &Bs[0][r * SMS + lc * 4];
        da[0] = __uint_as_float(f2tf32(av.x)); da[1] = __uint_as_float(f2tf32(av.y));
        da[2] = __uint_as_float(f2tf32(av.z)); da[3] = __uint_as_float(f2tf32(av.w));
        db[0] = __uint_as_float(f2tf32(bv.x)); db[1] = __uint_as_float(f2tf32(bv.y));
        db[2] = __uint_as_float(f2tf32(bv.z)); db[3] = __uint_as_float(f2tf32(bv.w));
    }
    __syncthreads();

    float4 a_next[2], b_next[2];

    for (int c = 0; c < nch; c++) {
        const int cur = c & 1;
        const int nxt = cur ^ 1;
        const bool has_next = (c + 1 < nch);

        if (has_next) {
            int k0 = (c + 1) * 16;
            #pragma unroll
            for (int i = 0; i < 2; i++) {
                int r = lr + i * 64;
                a_next[i] = *(const float4*)(A + (size_t)r * lda + k0 + lc * 4);
                b_next[i] = *(const float4*)(B + (size_t)r * ldb + k0 + lc * 4);
            }
        }

        const float* as = As[cur];
        const float* bs = Bs[cur];
        #pragma unroll
        for (int ks = 0; ks < 2; ks++) {
            const int k = ks * 8;
            uint32_t af[4][4], bf[4][2];
            #pragma unroll
            for (int mi = 0; mi < 4; mi++) {
                int rm = wm * 64 + mi * 16 + g;
                af[mi][0] = __float_as_uint(as[rm * SMS + k + t]);
                af[mi][1] = __float_as_uint(as[(rm + 8) * SMS + k + t]);
                af[mi][2] = __float_as_uint(as[rm * SMS + k + t + 4]);
                af[mi][3] = __float_as_uint(as[(rm + 8) * SMS + k + t + 4]);
            }
            #pragma unroll
            for (int ni = 0; ni < 4; ni++) {
                int cn = wn * 32 + ni * 8 + g;
                bf[ni][0] = __float_as_uint(bs[cn * SMS + k + t]);
                bf[ni][1] = __float_as_uint(bs[cn * SMS + k + t + 4]);
            }
            #pragma unroll
            for (int mi = 0; mi < 4; mi++)
                #pragma unroll
                for (int ni = 0; ni < 4; ni++)
                    mma_tf32(acc[mi][ni], af[mi], bf[ni]);
        }

        if (has_next) {
            #pragma unroll
            for (int i = 0; i < 2; i++) {
                int r = lr + i * 64;
                float* da = &As[nxt][r * SMS + lc * 4];
                float* db = &Bs[nxt][r * SMS + lc * 4];
                da[0] = __uint_as_float(f2tf32(a_next[i].x)); da[1] = __uint_as_float(f2tf32(a_next[i].y));
                da[2] = __uint_as_float(f2tf32(a_next[i].z)); da[3] = __uint_as_float(f2tf32(a_next[i].w));
                db[0] = __uint_as_float(f2tf32(b_next[i].x)); db[1] = __uint_as_float(f2tf32(b_next[i].y));
                db[2] = __uint_as_float(f2tf32(b_next[i].z)); db[3] = __uint_as_float(f2tf32(b_next[i].w));
            }
            __syncthreads();
        }
    }

    #pragma unroll
    for (int mi = 0; mi < 4; mi++) {
        const int r0 = blockIdx.y * 128 + wm * 64 + mi * 16 + g;
        #pragma unroll
        for (int ni = 0; ni < 4; ni++) {
            const int col = blockIdx.x * 128 + wn * 32 + ni * 8 + t * 2;
            float bv0 = 0.0f, bv1 = 0.0f;
            if (bias != nullptr) { bv0 = bias[col]; bv1 = bias[col + 1]; }
            float2 v0, v1;
            v0.x = acc[mi][ni][0] + bv0;
            v0.y = acc[mi][ni][1] + bv1;
            v1.x = acc[mi][ni][2] + bv0;
            v1.y = acc[mi][ni][3] + bv1;
            *(float2*)(C + (size_t)r0 * ldc + col)       = v0;
            *(float2*)(C + (size_t)(r0 + 8) * ldc + col) = v1;
        }
    }
}

// ---------------------------------------------------------------------------
// Fused flash attention (BMM1 + causal softmax + BMM2), tf32 mma.sync.
//   CTA = (q-block of 128 rows, head). 8 warps, each owns 16 full rows.
//   Online softmax; streams K/V tiles of 128 from g_qkv; writes g_ctx.
// ---------------------------------------------------------------------------
#define SQK 132   // Q/K smem row stride (floats): 4g+t lane pattern conflict-free
#define SVV 136   // V smem row stride: 8t+g lane pattern conflict-free
#define FLASH_SMEM ((2 * 128 * SQK + 128 * SVV) * 4)   // 204800 bytes

__global__ void __launch_bounds__(256)
flash_attn(const float* __restrict__ qkv, const uint8_t* __restrict__ mask,
           float* __restrict__ ctx)
{
    const int qblk = 15 - (int)(blockIdx.x >> 4);   // heavy CTAs first
    const int head = blockIdx.x & 15;

    extern __shared__ float sm[];
    float* Qs = sm;                    // [128][SQK]
    float* Ks = Qs + 128 * SQK;        // [128][SQK]  (rows = t-pos, cols = d)
    float* Vs = Ks + 128 * SQK;        // [128][SVV]  (rows = t-pos, cols = d)

    const int tid  = threadIdx.x;
    const int w    = tid >> 5;
    const int lane = tid & 31;
    const int g    = lane >> 2;
    const int t    = lane & 3;

    const float inv_norm = 0.08838834764831845f;   // 1/sqrt(128)

    // ---- load Q block once (tf32) ----
    const float* qsrc = qkv + (size_t)(qblk * 128) * QKV_N + head * 384;
    #pragma unroll
    for (int i = 0; i < 16; i++) {
        int idx = tid + i * 256;
        int r = idx >> 5, c4 = (idx & 31) * 4;
        float4 v = *(const float4*)(qsrc + (size_t)r * QKV_N + c4);
        uint4 u = make_uint4(f2tf32(v.x), f2tf32(v.y), f2tf32(v.z), f2tf32(v.w));
        *(uint4*)(Qs + r * SQK + c4) = u;
    }

    float o[16][4];
    #pragma unroll
    for (int ni = 0; ni < 16; ni++)
        #pragma unroll
        for (int q = 0; q < 4; q++) o[ni][q] = 0.0f;

    float m0 = -1e30f, m1 = -1e30f, l0 = 0.0f, l1 = 0.0f;

    const int row0g = qblk * 128 + w * 16 + g;
    const int row1g = row0g + 8;

    for (int j = 0; j <= qblk; j++) {
        __syncthreads();   // previous tile reads done
        // ---- load K & V tiles (tf32 / raw fp32 for V as tf32 container) ----
        const float* ksrc = qkv + (size_t)(j * 128) * QKV_N + head * 384 + 128;
        const float* vsrc = ksrc + 128;
        #pragma unroll
        for (int i = 0; i < 16; i++) {
            int idx = tid + i * 256;
            int r = idx >> 5, c4 = (idx & 31) * 4;
            float4 kv = *(const float4*)(ksrc + (size_t)r * QKV_N + c4);
            uint4 ku = make_uint4(f2tf32(kv.x), f2tf32(kv.y), f2tf32(kv.z), f2tf32(kv.w));
            *(uint4*)(Ks + r * SQK + c4) = ku;
            float4 vv = *(const float4*)(vsrc + (size_t)r * QKV_N + c4);
            uint4 vu = make_uint4(f2tf32(vv.x), f2tf32(vv.y), f2tf32(vv.z), f2tf32(vv.w));
            *(uint4*)(Vs + r * SVV + c4) = vu;
        }
        __syncthreads();

        // ---- S = Q . K^T (warp rows w*16..+15, all 128 cols) ----
        float s[16][4];
        #pragma unroll
        for (int ni = 0; ni < 16; ni++)
            #pragma unroll
            for (int q = 0; q < 4; q++) s[ni][q] = 0.0f;

        #pragma unroll
        for (int kk = 0; kk < 16; kk++) {
            uint32_t a[4];
            const float* qb = Qs + (w * 16) * SQK + kk * 8 + t;
            a[0] = __float_as_uint(qb[(size_t)g * SQK]);
            a[1] = __float_as_uint(qb[(size_t)(g + 8) * SQK]);
            a[2] = __float_as_uint(qb[(size_t)g * SQK + 4]);
            a[3] = __float_as_uint(qb[(size_t)(g + 8) * SQK + 4]);
            #pragma unroll
            for (int ni = 0; ni < 16; ni++) {
                uint32_t b[2];
                const float* kb = Ks + (size_t)(ni * 8 + g) * SQK + kk * 8 + t;
                b[0] = __float_as_uint(kb[0]);
                b[1] = __float_as_uint(kb[4]);
                mma_tf32(s[ni], a, b);
            }
        }

        // ---- scale + user mask + causal ----
        const uint8_t* mr0 = mask + (size_t)row0g * SEQ + j * 128;
        const uint8_t* mr1 = mask + (size_t)row1g * SEQ + j * 128;
        const bool diag = (j == qblk);
        #pragma unroll
        for (int ni = 0; ni < 16; ni++) {
            int c = ni * 8 + 2 * t;
            s[ni][0] *= inv_norm; s[ni][1] *= inv_norm;
            s[ni][2] *= inv_norm; s[ni][3] *= inv_norm;
            unsigned short mm0 = *(const unsigned short*)(mr0 + c);
            unsigned short mm1 = *(const unsigned short*)(mr1 + c);
            if (mm0 & 0x00FF) s[ni][0] = MASK_VAL;
            if (mm0 & 0xFF00) s[ni][1] = MASK_VAL;
            if (mm1 & 0x00FF) s[ni][2] = MASK_VAL;
            if (mm1 & 0xFF00) s[ni][3] = MASK_VAL;
            if (diag) {
                int cg = j * 128 + c;
                if (cg     > row0g) s[ni][0] = -1e30f;
                if (cg + 1 > row0g) s[ni][1] = -1e30f;
                if (cg     > row1g) s[ni][2] = -1e30f;
                if (cg + 1 > row1g) s[ni][3] = -1e30f;
            }
        }

        // ---- online softmax (rows g and g+8, warp-local) ----
        float mx0 = -1e30f, mx1 = -1e30f;
        #pragma unroll
        for (int ni = 0; ni < 16; ni++) {
            mx0 = fmaxf(mx0, fmaxf(s[ni][0], s[ni][1]));
            mx1 = fmaxf(mx1, fmaxf(s[ni][2], s[ni][3]));
        }
        mx0 = fmaxf(mx0, __shfl_xor_sync(0xFFFFFFFFu, mx0, 1));
        mx0 = fmaxf(mx0, __shfl_xor_sync(0xFFFFFFFFu, mx0, 2));
        mx1 = fmaxf(mx1, __shfl_xor_sync(0xFFFFFFFFu, mx1, 1));
        mx1 = fmaxf(mx1, __shfl_xor_sync(0xFFFFFFFFu, mx1, 2));

        float mn0 = fmaxf(m0, mx0), mn1 = fmaxf(m1, mx1);
        float al0 = __expf(m0 - mn0), al1 = __expf(m1 - mn1);
        m0 = mn0; m1 = mn1;

        float sum0 = 0.0f, sum1 = 0.0f;
        #pragma unroll
        for (int ni = 0; ni < 16; ni++) {
            s[ni][0] = __expf(s[ni][0] - mn0);
            s[ni][1] = __expf(s[ni][1] - mn0);
            s[ni][2] = __expf(s[ni][2] - mn1);
            s[ni][3] = __expf(s[ni][3] - mn1);
            sum0 += s[ni][0] + s[ni][1];
            sum1 += s[ni][2] + s[ni][3];
        }
        sum0 += __shfl_xor_sync(0xFFFFFFFFu, sum0, 1);
        sum0 += __shfl_xor_sync(0xFFFFFFFFu, sum0, 2);
        sum1 += __shfl_xor_sync(0xFFFFFFFFu, sum1, 1);
        sum1 += __shfl_xor_sync(0xFFFFFFFFu, sum1, 2);
        l0 = l0 * al0 + sum0;
        l1 = l1 * al1 + sum1;

        #pragma unroll
        for (int ni = 0; ni < 16; ni++) {
            o[ni][0] *= al0; o[ni][1] *= al0;
            o[ni][2] *= al1; o[ni][3] *= al1;
        }

        // ---- O += P . V  (P rebuilt as A-fragments via shfl) ----
        const int src0 = (lane & ~3) | (t >> 1);
        const bool odd = (t & 1);
        #pragma unroll
        for (int kk = 0; kk < 16; kk++) {
            float v00 = __shfl_sync(0xFFFFFFFFu, s[kk][0], src0);
            float v01 = __shfl_sync(0xFFFFFFFFu, s[kk][1], src0);
            float v10 = __shfl_sync(0xFFFFFFFFu, s[kk][0], src0 + 2);
            float v11 = __shfl_sync(0xFFFFFFFFu, s[kk][1], src0 + 2);
            float w00 = __shfl_sync(0xFFFFFFFFu, s[kk][2], src0);
            float w01 = __shfl_sync(0xFFFFFFFFu, s[kk][3], src0);
            float w10 = __shfl_sync(0xFFFFFFFFu, s[kk][2], src0 + 2);
            float w11 = __shfl_sync(0xFFFFFFFFu, s[kk][3], src0 + 2);
            uint32_t a[4];
            a[0] = f2tf32(odd ? v01 : v00);
            a[1] = f2tf32(odd ? w01 : w00);
            a[2] = f2tf32(odd ? v11 : v10);
            a[3] = f2tf32(odd ? w11 : w10);
            #pragma unroll
            for (int ni = 0; ni < 16; ni++) {
                uint32_t b[2];
                const float* vb = Vs + (size_t)(kk * 8 + t) * SVV + ni * 8 + g;
                b[0] = __float_as_uint(vb[0]);
                b[1] = __float_as_uint(vb[4 * SVV]);
                mma_tf32(o[ni], a, b);
            }
        }
    }

    // ---- epilogue: O / l -> ctx[row, head*128 + d] ----
    const float il0 = 1.0f / l0;
    const float il1 = 1.0f / l1;
    float* c0 = ctx + (size_t)row0g * HID + head * HDIM;
    float* c1 = ctx + (size_t)row1g * HID + head * HDIM;
    #pragma unroll
    for (int ni = 0; ni < 16; ni++) {
        int c = ni * 8 + 2 * t;
        float2 p0 = make_float2(o[ni][0] * il0, o[ni][1] * il0);
        float2 p1 = make_float2(o[ni][2] * il1, o[ni][3] * il1);
        *(float2*)(c0 + c) = p0;
        *(float2*)(c1 + c) = p1;
    }
}

__global__ void copy_bias(const float* __restrict__ b, float* __restrict__ out)
{
    int i = blockIdx.x * 256 + threadIdx.x;
    if (i < HID) out[i] = b[i];
}

// ============================================================================
extern "C" void kernel_launch(void* const* d_in, const int* in_sizes, int n_in,
                              void* d_out, int out_size)
{
    const float*   hs     = (const float*)d_in[0];   // [2048, 1, 2048]
    const float*   w_qkv  = (const float*)d_in[1];   // [6144, 2048]
    const float*   b_qkv  = (const float*)d_in[2];   // [6144]
    const float*   w_proj = (const float*)d_in[3];   // [2048, 2048]
    const float*   b_proj = (const float*)d_in[4];   // [2048]
    const uint8_t* mask   = (const uint8_t*)d_in[5]; // [1,1,2048,2048] bool

    float* qkv; cudaGetSymbolAddress((void**)&qkv, g_qkv);
    float* ctx; cudaGetSymbolAddress((void**)&ctx, g_ctx);
    float* out = (float*)d_out;

    static bool attr_set = false;
    if (!attr_set) {
        cudaFuncSetAttribute(flash_attn, cudaFuncAttributeMaxDynamicSharedMemorySize, FLASH_SMEM);
        attr_set = true;
    }

    // 1) fused QKV GEMM: qkv[s,o] = hs[s,:] . w_qkv[o,:] + b_qkv[o]
    gemm_mma<<<dim3(QKV_N / 128, SEQ / 128), 256>>>(
        hs, HID, w_qkv, HID, qkv, QKV_N, b_qkv, HID);

    // 2) fused attention: BMM1 + causal softmax + BMM2 -> ctx
    flash_attn<<<dim3(16 * NHEAD), 256, FLASH_SMEM>>>(qkv, mask, ctx);

    // 3) output projection (bias returned separately)
    gemm_mma<<<dim3(HID / 128, SEQ / 128), 256>>>(
        ctx, HID, w_proj, HID, out, HID, nullptr, HID);

    // 4) tuple second element: b_proj appended after the [S*H] projection output
    if (out_size >= SEQ * HID + HID) {
        copy_bias<<<(HID + 255) / 256, 256>>>(b_proj, out + (size_t)SEQ * HID);
    }
}

// round 5
// speedup vs baseline: 3.3850x; 1.0163x over previous
#include <cuda_runtime.h>
#include <math.h>
#include <stdint.h>

// Problem constants (fixed shapes from reference)
#define SEQ   2048
#define HID   2048
#define NHEAD 16
#define HDIM  128
#define QKV_N (3 * HID)   // 6144
#define MASK_VAL (-10000.0f)

// -------- device scratch (static; no allocations allowed) --------
__device__ float g_qkv[SEQ * QKV_N];        // [s, 3h] QKV output (tf32-rounded bits)
__device__ float g_ctx[SEQ * HID];          // [s, h] context (tf32-rounded bits)
__device__ float g_hs[SEQ * HID];           // tf32-rounded hidden_states
__device__ float g_wqkv[QKV_N * HID];       // tf32-rounded w_qkv
__device__ float g_wproj[HID * HID];        // tf32-rounded w_proj

// ---------------------------------------------------------------------------
// helpers
// ---------------------------------------------------------------------------
__device__ __forceinline__ uint32_t f2tf32(float f) {
    uint32_t u;
    asm("cvt.rna.tf32.f32 %0, %1;" : "=r"(u) : "f"(f));
    return u;
}

__device__ __forceinline__ void mma_tf32(float* d, const uint32_t* a, const uint32_t* b) {
    asm volatile(
        "mma.sync.aligned.m16n8k8.row.col.f32.tf32.tf32.f32 "
        "{%0,%1,%2,%3}, {%4,%5,%6,%7}, {%8,%9}, {%0,%1,%2,%3};"
        : "+f"(d[0]), "+f"(d[1]), "+f"(d[2]), "+f"(d[3])
        : "r"(a[0]), "r"(a[1]), "r"(a[2]), "r"(a[3]), "r"(b[0]), "r"(b[1]));
}

__device__ __forceinline__ void cp16(void* dst_smem, const void* src) {
    uint32_t d = (uint32_t)__cvta_generic_to_shared(dst_smem);
    asm volatile("cp.async.cg.shared.global [%0], [%1], 16;" :: "r"(d), "l"(src));
}
#define CP_COMMIT() asm volatile("cp.async.commit_group;" ::: "memory")
#define CP_WAIT(N)  asm volatile("cp.async.wait_group %0;" :: "n"(N) : "memory")

// ---------------------------------------------------------------------------
// pre-round fp32 -> tf32 bits (elementwise, float4)
// ---------------------------------------------------------------------------
__global__ void __launch_bounds__(256)
prep_tf32(const float* __restrict__ src, float* __restrict__ dst, int n4)
{
    int i = blockIdx.x * 256 + threadIdx.x;
    if (i < n4) {
        float4 v = ((const float4*)src)[i];
        uint4 u = make_uint4(f2tf32(v.x), f2tf32(v.y), f2tf32(v.z), f2tf32(v.w));
        ((uint4*)dst)[i] = u;
    }
}

// ---------------------------------------------------------------------------
// tf32 mma.sync GEMM: C = A * B^T + bias.  Inputs already tf32-rounded.
//   CTA tile 128x128, BK=16, 3-stage cp.async pipeline.
//   256 threads = 8 warps (2 M x 4 N), warp tile 64x32.
//   ROUND_OUT: round outputs to tf32 bits (for qkv intermediate).
// ---------------------------------------------------------------------------
#define SMS 20               // smem row stride (floats)
#define GSTG 3
#define GEMM_SMEM (GSTG * 2 * 128 * SMS * 4)   // 61440 bytes

template<bool ROUND_OUT>
__global__ void __launch_bounds__(256)
gemm_mma(const float* __restrict__ A, int lda,
         const float* __restrict__ B, int ldb,
         float* __restrict__ C, int ldc,
         const float* __restrict__ bias, int K)
{
    extern __shared__ float smg[];
    float* As = smg;                          // [GSTG][128*SMS]
    float* Bs = smg + GSTG * 128 * SMS;

    const int tid = threadIdx.x;
    const int wid = tid >> 5;
    const int lane = tid & 31;
    const int g = lane >> 2;
    const int t = lane & 3;
    const int wm = wid & 1;
    const int wn = wid >> 1;

    A += (size_t)(blockIdx.y * 128) * lda;
    B += (size_t)(blockIdx.x * 128) * ldb;

    const int lr = tid >> 2;        // row 0..63 (second row +64)
    const int lc = (tid & 3) * 4;   // col group

    float acc[4][4][4];
    #pragma unroll
    for (int mi = 0; mi < 4; mi++)
        #pragma unroll
        for (int ni = 0; ni < 4; ni++)
            #pragma unroll
            for (int q = 0; q < 4; q++) acc[mi][ni][q] = 0.0f;

    const int nch = K >> 4;

    // issue one stage's loads as one cp.async group
    auto issue = [&](int st, int k0) {
        float* as = As + st * 128 * SMS;
        float* bs = Bs + st * 128 * SMS;
        #pragma unroll
        for (int i = 0; i < 2; i++) {
            int r = lr + i * 64;
            cp16(as + r * SMS + lc, A + (size_t)r * lda + k0 + lc);
            cp16(bs + r * SMS + lc, B + (size_t)r * ldb + k0 + lc);
        }
        CP_COMMIT();
    };

    issue(0, 0);
    if (nch > 1) issue(1, 16);

    for (int c = 0; c < nch; c++) {
        if (c + 1 < nch) { CP_WAIT(1); } else { CP_WAIT(0); }
        __syncthreads();
        if (c + 2 < nch) issue((c + 2) % GSTG, (c + 2) * 16);

        const float* as = As + (c % GSTG) * 128 * SMS;
        const float* bs = Bs + (c % GSTG) * 128 * SMS;
        #pragma unroll
        for (int ks = 0; ks < 2; ks++) {
            const int k = ks * 8;
            uint32_t af[4][4], bf[4][2];
            #pragma unroll
            for (int mi = 0; mi < 4; mi++) {
                int rm = wm * 64 + mi * 16 + g;
                af[mi][0] = __float_as_uint(as[rm * SMS + k + t]);
                af[mi][1] = __float_as_uint(as[(rm + 8) * SMS + k + t]);
                af[mi][2] = __float_as_uint(as[rm * SMS + k + t + 4]);
                af[mi][3] = __float_as_uint(as[(rm + 8) * SMS + k + t + 4]);
            }
            #pragma unroll
            for (int ni = 0; ni < 4; ni++) {
                int cn = wn * 32 + ni * 8 + g;
                bf[ni][0] = __float_as_uint(bs[cn * SMS + k + t]);
                bf[ni][1] = __float_as_uint(bs[cn * SMS + k + t + 4]);
            }
            #pragma unroll
            for (int mi = 0; mi < 4; mi++)
                #pragma unroll
                for (int ni = 0; ni < 4; ni++)
                    mma_tf32(acc[mi][ni], af[mi], bf[ni]);
        }
    }

    // epilogue
    #pragma unroll
    for (int mi = 0; mi < 4; mi++) {
        const int r0 = blockIdx.y * 128 + wm * 64 + mi * 16 + g;
        #pragma unroll
        for (int ni = 0; ni < 4; ni++) {
            const int col = blockIdx.x * 128 + wn * 32 + ni * 8 + t * 2;
            float bv0 = 0.0f, bv1 = 0.0f;
            if (bias != nullptr) { bv0 = bias[col]; bv1 = bias[col + 1]; }
            float r00 = acc[mi][ni][0] + bv0;
            float r01 = acc[mi][ni][1] + bv1;
            float r10 = acc[mi][ni][2] + bv0;
            float r11 = acc[mi][ni][3] + bv1;
            float2 v0, v1;
            if (ROUND_OUT) {
                v0 = make_float2(__uint_as_float(f2tf32(r00)), __uint_as_float(f2tf32(r01)));
                v1 = make_float2(__uint_as_float(f2tf32(r10)), __uint_as_float(f2tf32(r11)));
            } else {
                v0 = make_float2(r00, r01);
                v1 = make_float2(r10, r11);
            }
            *(float2*)(C + (size_t)r0 * ldc + col)       = v0;
            *(float2*)(C + (size_t)(r0 + 8) * ldc + col) = v1;
        }
    }
}

// ---------------------------------------------------------------------------
// Fused flash attention (BMM1 + causal softmax + BMM2), tf32 mma.sync.
//   qkv already tf32-rounded -> raw cp.async loads, no cvt in hot loop.
//   Split waits: V load overlaps the S=QK^T + softmax phase.
// ---------------------------------------------------------------------------
#define SQK 132
#define SVV 136
#define FLASH_SMEM ((2 * 128 * SQK + 128 * SVV) * 4)   // 204800 bytes

__global__ void __launch_bounds__(256)
flash_attn(const float* __restrict__ qkv, const uint8_t* __restrict__ mask,
           float* __restrict__ ctx)
{
    const int qblk = 15 - (int)(blockIdx.x >> 4);   // heavy CTAs first
    const int head = blockIdx.x & 15;

    extern __shared__ float sm[];
    float* Qs = sm;                    // [128][SQK]
    float* Ks = Qs + 128 * SQK;        // [128][SQK]
    float* Vs = Ks + 128 * SQK;        // [128][SVV]

    const int tid  = threadIdx.x;
    const int w    = tid >> 5;
    const int lane = tid & 31;
    const int g    = lane >> 2;
    const int t    = lane & 3;

    const float inv_norm = 0.08838834764831845f;   // 1/sqrt(128)

    const int ldr = tid >> 5;           // base row 0..7 (step 8)
    const int ldc4 = (tid & 31) * 4;    // col group

    // ---- Q block: raw cp.async (group 0) ----
    const float* qsrc = qkv + (size_t)(qblk * 128) * QKV_N + head * 384;
    #pragma unroll
    for (int i = 0; i < 16; i++) {
        int r = ldr + i * 8;
        cp16(Qs + r * SQK + ldc4, qsrc + (size_t)r * QKV_N + ldc4);
    }
    CP_COMMIT();

    float o[16][4];
    #pragma unroll
    for (int ni = 0; ni < 16; ni++)
        #pragma unroll
        for (int q = 0; q < 4; q++) o[ni][q] = 0.0f;

    float m0 = -1e30f, m1 = -1e30f, l0 = 0.0f, l1 = 0.0f;

    const int row0g = qblk * 128 + w * 16 + g;
    const int row1g = row0g + 8;

    for (int j = 0; j <= qblk; j++) {
        __syncthreads();   // previous tile fully consumed
        const float* ksrc = qkv + (size_t)(j * 128) * QKV_N + head * 384 + 128;
        const float* vsrc = ksrc + 128;
        #pragma unroll
        for (int i = 0; i < 16; i++) {
            int r = ldr + i * 8;
            cp16(Ks + r * SQK + ldc4, ksrc + (size_t)r * QKV_N + ldc4);
        }
        CP_COMMIT();                    // K group
        #pragma unroll
        for (int i = 0; i < 16; i++) {
            int r = ldr + i * 8;
            cp16(Vs + r * SVV + ldc4, vsrc + (size_t)r * QKV_N + ldc4);
        }
        CP_COMMIT();                    // V group

        CP_WAIT(1);                     // K (and Q on iter 0) arrived
        __syncthreads();

        // ---- S = Q . K^T ----
        float s[16][4];
        #pragma unroll
        for (int ni = 0; ni < 16; ni++)
            #pragma unroll
            for (int q = 0; q < 4; q++) s[ni][q] = 0.0f;

        #pragma unroll
        for (int kk = 0; kk < 16; kk++) {
            uint32_t a[4];
            const float* qb = Qs + (w * 16) * SQK + kk * 8 + t;
            a[0] = __float_as_uint(qb[(size_t)g * SQK]);
            a[1] = __float_as_uint(qb[(size_t)(g + 8) * SQK]);
            a[2] = __float_as_uint(qb[(size_t)g * SQK + 4]);
            a[3] = __float_as_uint(qb[(size_t)(g + 8) * SQK + 4]);
            #pragma unroll
            for (int ni = 0; ni < 16; ni++) {
                uint32_t b[2];
                const float* kb = Ks + (size_t)(ni * 8 + g) * SQK + kk * 8 + t;
                b[0] = __float_as_uint(kb[0]);
                b[1] = __float_as_uint(kb[4]);
                mma_tf32(s[ni], a, b);
            }
        }

        // ---- scale + user mask + causal ----
        const uint8_t* mr0 = mask + (size_t)row0g * SEQ + j * 128;
        const uint8_t* mr1 = mask + (size_t)row1g * SEQ + j * 128;
        const bool diag = (j == qblk);
        #pragma unroll
        for (int ni = 0; ni < 16; ni++) {
            int c = ni * 8 + 2 * t;
            s[ni][0] *= inv_norm; s[ni][1] *= inv_norm;
            s[ni][2] *= inv_norm; s[ni][3] *= inv_norm;
            unsigned short mm0 = *(const unsigned short*)(mr0 + c);
            unsigned short mm1 = *(const unsigned short*)(mr1 + c);
            if (mm0 & 0x00FF) s[ni][0] = MASK_VAL;
            if (mm0 & 0xFF00) s[ni][1] = MASK_VAL;
            if (mm1 & 0x00FF) s[ni][2] = MASK_VAL;
            if (mm1 & 0xFF00) s[ni][3] = MASK_VAL;
            if (diag) {
                int cg = j * 128 + c;
                if (cg     > row0g) s[ni][0] = -1e30f;
                if (cg + 1 > row0g) s[ni][1] = -1e30f;
                if (cg     > row1g) s[ni][2] = -1e30f;
                if (cg + 1 > row1g) s[ni][3] = -1e30f;
            }
        }

        // ---- online softmax ----
        float mx0 = -1e30f, mx1 = -1e30f;
        #pragma unroll
        for (int ni = 0; ni < 16; ni++) {
            mx0 = fmaxf(mx0, fmaxf(s[ni][0], s[ni][1]));
            mx1 = fmaxf(mx1, fmaxf(s[ni][2], s[ni][3]));
        }
        mx0 = fmaxf(mx0, __shfl_xor_sync(0xFFFFFFFFu, mx0, 1));
        mx0 = fmaxf(mx0, __shfl_xor_sync(0xFFFFFFFFu, mx0, 2));
        mx1 = fmaxf(mx1, __shfl_xor_sync(0xFFFFFFFFu, mx1, 1));
        mx1 = fmaxf(mx1, __shfl_xor_sync(0xFFFFFFFFu, mx1, 2));

        float mn0 = fmaxf(m0, mx0), mn1 = fmaxf(m1, mx1);
        float al0 = __expf(m0 - mn0), al1 = __expf(m1 - mn1);
        m0 = mn0; m1 = mn1;

        float sum0 = 0.0f, sum1 = 0.0f;
        #pragma unroll
        for (int ni = 0; ni < 16; ni++) {
            s[ni][0] = __expf(s[ni][0] - mn0);
            s[ni][1] = __expf(s[ni][1] - mn0);
            s[ni][2] = __expf(s[ni][2] - mn1);
            s[ni][3] = __expf(s[ni][3] - mn1);
            sum0 += s[ni][0] + s[ni][1];
            sum1 += s[ni][2] + s[ni][3];
        }
        sum0 += __shfl_xor_sync(0xFFFFFFFFu, sum0, 1);
        sum0 += __shfl_xor_sync(0xFFFFFFFFu, sum0, 2);
        sum1 += __shfl_xor_sync(0xFFFFFFFFu, sum1, 1);
        sum1 += __shfl_xor_sync(0xFFFFFFFFu, sum1, 2);
        l0 = l0 * al0 + sum0;
        l1 = l1 * al1 + sum1;

        #pragma unroll
        for (int ni = 0; ni < 16; ni++) {
            o[ni][0] *= al0; o[ni][1] *= al0;
            o[ni][2] *= al1; o[ni][3] *= al1;
        }

        CP_WAIT(0);        // V arrived (overlapped with S + softmax)
        __syncthreads();

        // ---- O += P . V (P rebuilt as A-fragments via shfl) ----
        const int src0 = (lane & ~3) | (t >> 1);
        const bool odd = (t & 1);
        #pragma unroll
        for (int kk = 0; kk < 16; kk++) {
            float v00 = __shfl_sync(0xFFFFFFFFu, s[kk][0], src0);
            float v01 = __shfl_sync(0xFFFFFFFFu, s[kk][1], src0);
            float v10 = __shfl_sync(0xFFFFFFFFu, s[kk][0], src0 + 2);
            float v11 = __shfl_sync(0xFFFFFFFFu, s[kk][1], src0 + 2);
            float w00 = __shfl_sync(0xFFFFFFFFu, s[kk][2], src0);
            float w01 = __shfl_sync(0xFFFFFFFFu, s[kk][3], src0);
            float w10 = __shfl_sync(0xFFFFFFFFu, s[kk][2], src0 + 2);
            float w11 = __shfl_sync(0xFFFFFFFFu, s[kk][3], src0 + 2);
            uint32_t a[4];
            a[0] = f2tf32(odd ? v01 : v00);
            a[1] = f2tf32(odd ? w01 : w00);
            a[2] = f2tf32(odd ? v11 : v10);
            a[3] = f2tf32(odd ? w11 : w10);
            #pragma unroll
            for (int ni = 0; ni < 16; ni++) {
                uint32_t b[2];
                const float* vb = Vs + (size_t)(kk * 8 + t) * SVV + ni * 8 + g;
                b[0] = __float_as_uint(vb[0]);
                b[1] = __float_as_uint(vb[4 * SVV]);
                mma_tf32(o[ni], a, b);
            }
        }
    }

    // ---- epilogue: O / l -> ctx (tf32-rounded for the proj GEMM) ----
    const float il0 = 1.0f / l0;
    const float il1 = 1.0f / l1;
    float* c0 = ctx + (size_t)row0g * HID + head * HDIM;
    float* c1 = ctx + (size_t)row1g * HID + head * HDIM;
    #pragma unroll
    for (int ni = 0; ni < 16; ni++) {
        int c = ni * 8 + 2 * t;
        uint2 p0 = make_uint2(f2tf32(o[ni][0] * il0), f2tf32(o[ni][1] * il0));
        uint2 p1 = make_uint2(f2tf32(o[ni][2] * il1), f2tf32(o[ni][3] * il1));
        *(uint2*)(c0 + c) = p0;
        *(uint2*)(c1 + c) = p1;
    }
}

__global__ void copy_bias(const float* __restrict__ b, float* __restrict__ out)
{
    int i = blockIdx.x * 256 + threadIdx.x;
    if (i < HID) out[i] = b[i];
}

// ============================================================================
extern "C" void kernel_launch(void* const* d_in, const int* in_sizes, int n_in,
                              void* d_out, int out_size)
{
    const float*   hs     = (const float*)d_in[0];   // [2048, 1, 2048]
    const float*   w_qkv  = (const float*)d_in[1];   // [6144, 2048]
    const float*   b_qkv  = (const float*)d_in[2];   // [6144]
    const float*   w_proj = (const float*)d_in[3];   // [2048, 2048]
    const float*   b_proj = (const float*)d_in[4];   // [2048]
    const uint8_t* mask   = (const uint8_t*)d_in[5]; // [1,1,2048,2048] bool

    float *qkv, *ctx, *phs, *pwqkv, *pwproj;
    cudaGetSymbolAddress((void**)&qkv,    g_qkv);
    cudaGetSymbolAddress((void**)&ctx,    g_ctx);
    cudaGetSymbolAddress((void**)&phs,    g_hs);
    cudaGetSymbolAddress((void**)&pwqkv,  g_wqkv);
    cudaGetSymbolAddress((void**)&pwproj, g_wproj);
    float* out = (float*)d_out;

    static bool attr_set = false;
    if (!attr_set) {
        cudaFuncSetAttribute(flash_attn, cudaFuncAttributeMaxDynamicSharedMemorySize, FLASH_SMEM);
        cudaFuncSetAttribute(gemm_mma<true>,  cudaFuncAttributeMaxDynamicSharedMemorySize, GEMM_SMEM);
        cudaFuncSetAttribute(gemm_mma<false>, cudaFuncAttributeMaxDynamicSharedMemorySize, GEMM_SMEM);
        attr_set = true;
    }

    // 0) pre-round inputs to tf32 bits
    prep_tf32<<<(SEQ * HID / 4 + 255) / 256, 256>>>(hs,     phs,    SEQ * HID / 4);
    prep_tf32<<<(QKV_N * HID / 4 + 255) / 256, 256>>>(w_qkv, pwqkv,  QKV_N * HID / 4);
    prep_tf32<<<(HID * HID / 4 + 255) / 256, 256>>>(w_proj, pwproj, HID * HID / 4);

    // 1) fused QKV GEMM (tf32-rounded output)
    gemm_mma<true><<<dim3(QKV_N / 128, SEQ / 128), 256, GEMM_SMEM>>>(
        phs, HID, pwqkv, HID, qkv, QKV_N, b_qkv, HID);

    // 2) fused attention: BMM1 + causal softmax + BMM2 -> ctx (tf32-rounded)
    flash_attn<<<dim3(16 * NHEAD), 256, FLASH_SMEM>>>(qkv, mask, ctx);

    // 3) output projection (raw fp32 output)
    gemm_mma<false><<<dim3(HID / 128, SEQ / 128), 256, GEMM_SMEM>>>(
        ctx, HID, pwproj, HID, out, HID, nullptr, HID);

    // 4) tuple second element: b_proj appended after the [S*H] projection output
    if (out_size >= SEQ * HID + HID) {
        copy_bias<<<(HID + 255) / 256, 256>>>(b_proj, out + (size_t)SEQ * HID);
    }
}

// round 6
// speedup vs baseline: 6.2710x; 1.8526x over previous
#include <cuda_runtime.h>
#include <cuda_fp16.h>
#include <math.h>
#include <stdint.h>

// Problem constants (fixed shapes from reference)
#define SEQ   2048
#define HID   2048
#define NHEAD 16
#define HDIM  128
#define QKV_N (3 * HID)   // 6144
#define MASK_VAL (-10000.0f)

// -------- device scratch (static; no allocations allowed) --------
__device__ __half g_qkv[SEQ * QKV_N];     // [s, 3h] QKV output (fp16)
__device__ __half g_ctx[SEQ * HID];       // [s, h] context (fp16)
__device__ __half g_hs[SEQ * HID];        // fp16 hidden_states
__device__ __half g_wqkv[QKV_N * HID];    // fp16 w_qkv
__device__ __half g_wproj[HID * HID];     // fp16 w_proj

// ---------------------------------------------------------------------------
// helpers
// ---------------------------------------------------------------------------
__device__ __forceinline__ uint32_t pack_h2(float lo, float hi) {
    __half2 h = __floats2half2_rn(lo, hi);
    return *reinterpret_cast<uint32_t*>(&h);
}

__device__ __forceinline__ void mma_f16(float* d, const uint32_t* a, const uint32_t* b) {
    asm volatile(
        "mma.sync.aligned.m16n8k16.row.col.f32.f16.f16.f32 "
        "{%0,%1,%2,%3}, {%4,%5,%6,%7}, {%8,%9}, {%0,%1,%2,%3};"
        : "+f"(d[0]), "+f"(d[1]), "+f"(d[2]), "+f"(d[3])
        : "r"(a[0]), "r"(a[1]), "r"(a[2]), "r"(a[3]), "r"(b[0]), "r"(b[1]));
}

__device__ __forceinline__ void ldsm_x4(uint32_t* r, const void* p) {
    uint32_t a = (uint32_t)__cvta_generic_to_shared(p);
    asm volatile("ldmatrix.sync.aligned.m8n8.x4.shared.b16 {%0,%1,%2,%3}, [%4];"
        : "=r"(r[0]), "=r"(r[1]), "=r"(r[2]), "=r"(r[3]) : "r"(a));
}

__device__ __forceinline__ void ldsm_x4_t(uint32_t* r, const void* p) {
    uint32_t a = (uint32_t)__cvta_generic_to_shared(p);
    asm volatile("ldmatrix.sync.aligned.m8n8.x4.trans.shared.b16 {%0,%1,%2,%3}, [%4];"
        : "=r"(r[0]), "=r"(r[1]), "=r"(r[2]), "=r"(r[3]) : "r"(a));
}

__device__ __forceinline__ void cp16(void* dst_smem, const void* src) {
    uint32_t d = (uint32_t)__cvta_generic_to_shared(dst_smem);
    asm volatile("cp.async.cg.shared.global [%0], [%1], 16;" :: "r"(d), "l"(src));
}
#define CP_COMMIT() asm volatile("cp.async.commit_group;" ::: "memory")
#define CP_WAIT(N)  asm volatile("cp.async.wait_group %0;" :: "n"(N) : "memory")

// ---------------------------------------------------------------------------
// fp32 -> fp16 conversion (4 elems/thread)
// ---------------------------------------------------------------------------
__global__ void __launch_bounds__(256)
prep_h(const float* __restrict__ src, __half* __restrict__ dst, int n4)
{
    int i = blockIdx.x * 256 + threadIdx.x;
    if (i < n4) {
        float4 v = ((const float4*)src)[i];
        uint2 u = make_uint2(pack_h2(v.x, v.y), pack_h2(v.z, v.w));
        ((uint2*)dst)[i] = u;
    }
}

// ---------------------------------------------------------------------------
// fp16 mma.sync GEMM: C = A * B^T + bias.
//   A[M,K] fp16 row-major, B[N,K] fp16 row-major.
//   CTA 128x128, BK=32, 3-stage cp.async, 8 warps (2M x 4N), warp 64x32.
//   Fragments via ldmatrix. OUT_HALF -> C fp16, else fp32.
// ---------------------------------------------------------------------------
#define HSM 40               // smem row stride in halves (32 data + 8 pad)
#define GSTG 3
#define GEMM_SMEM (GSTG * 2 * 128 * HSM * 2)   // 61440 bytes

template<bool OUT_HALF>
__global__ void __launch_bounds__(256)
gemm_h(const __half* __restrict__ A, int lda,
       const __half* __restrict__ B, int ldb,
       void* __restrict__ Cv, int ldc,
       const float* __restrict__ bias, int K)
{
    extern __shared__ __half smh[];
    __half* As = smh;                          // [GSTG][128*HSM]
    __half* Bs = smh + GSTG * 128 * HSM;

    const int tid = threadIdx.x;
    const int wid = tid >> 5;
    const int lane = tid & 31;
    const int t = lane & 3;
    const int g = lane >> 2;
    const int wm = wid & 1;
    const int wn = wid >> 1;

    A += (size_t)(blockIdx.y * 128) * lda;
    B += (size_t)(blockIdx.x * 128) * ldb;

    // cp.async addressing: 128 rows x 4 segs(16B) per matrix = 512 / 256 thr
    const int lrow = tid >> 1;           // base row (second +64? no: idx scheme below)

    float acc[4][4][4];
    #pragma unroll
    for (int mi = 0; mi < 4; mi++)
        #pragma unroll
        for (int ni = 0; ni < 4; ni++)
            #pragma unroll
            for (int q = 0; q < 4; q++) acc[mi][ni][q] = 0.0f;

    const int nch = K >> 5;   // K / 32

    auto issue = [&](int st, int k0) {
        __half* as = As + st * 128 * HSM;
        __half* bs = Bs + st * 128 * HSM;
        #pragma unroll
        for (int i = 0; i < 2; i++) {
            int idx = tid + i * 256;
            int r = idx >> 2;            // 0..127
            int sgo = (idx & 3) * 8;     // halves
            cp16(as + r * HSM + sgo, A + (size_t)r * lda + k0 + sgo);
            cp16(bs + r * HSM + sgo, B + (size_t)r * ldb + k0 + sgo);
        }
        CP_COMMIT();
    };

    issue(0, 0);
    if (nch > 1) issue(1, 32);

    // ldmatrix lane addressing (constant per thread)
    const int a_row = wm * 64 + (lane & 15);            // + mi*16
    const int a_col = (lane >> 4) << 3;                 // + ks*16
    const int b_row = wn * 32 + ((lane >> 4) << 3) + (lane & 7);   // + np*16
    const int b_col = ((lane >> 3) & 1) << 3;           // + ks*16

    for (int c = 0; c < nch; c++) {
        if (c + 1 < nch) { CP_WAIT(1); } else { CP_WAIT(0); }
        __syncthreads();
        if (c + 2 < nch) issue((c + 2) % GSTG, (c + 2) * 32);

        const __half* as = As + (c % GSTG) * 128 * HSM;
        const __half* bs = Bs + (c % GSTG) * 128 * HSM;
        #pragma unroll
        for (int ks = 0; ks < 2; ks++) {
            uint32_t af[4][4], bf[2][4];
            #pragma unroll
            for (int mi = 0; mi < 4; mi++)
                ldsm_x4(af[mi], as + (size_t)(a_row + mi * 16) * HSM + ks * 16 + a_col);
            #pragma unroll
            for (int np = 0; np < 2; np++)
                ldsm_x4(bf[np], bs + (size_t)(b_row + np * 16) * HSM + ks * 16 + b_col);
            #pragma unroll
            for (int mi = 0; mi < 4; mi++)
                #pragma unroll
                for (int ni = 0; ni < 4; ni++)
                    mma_f16(acc[mi][ni], af[mi], &bf[ni >> 1][(ni & 1) * 2]);
        }
    }

    // epilogue
    #pragma unroll
    for (int mi = 0; mi < 4; mi++) {
        const int r0 = blockIdx.y * 128 + wm * 64 + mi * 16 + g;
        #pragma unroll
        for (int ni = 0; ni < 4; ni++) {
            const int col = blockIdx.x * 128 + wn * 32 + ni * 8 + t * 2;
            float bv0 = 0.0f, bv1 = 0.0f;
            if (bias != nullptr) { bv0 = bias[col]; bv1 = bias[col + 1]; }
            float r00 = acc[mi][ni][0] + bv0;
            float r01 = acc[mi][ni][1] + bv1;
            float r10 = acc[mi][ni][2] + bv0;
            float r11 = acc[mi][ni][3] + bv1;
            if (OUT_HALF) {
                __half* C = (__half*)Cv;
                *(uint32_t*)(C + (size_t)r0 * ldc + col)       = pack_h2(r00, r01);
                *(uint32_t*)(C + (size_t)(r0 + 8) * ldc + col) = pack_h2(r10, r11);
            } else {
                float* C = (float*)Cv;
                *(float2*)(C + (size_t)r0 * ldc + col)       = make_float2(r00, r01);
                *(float2*)(C + (size_t)(r0 + 8) * ldc + col) = make_float2(r10, r11);
            }
        }
    }
}

// ---------------------------------------------------------------------------
// Fused fp16 flash attention (BMM1 + causal softmax + BMM2).
//   CTA = (q-block 128 rows, head). 8 warps x 16 rows. Online softmax.
//   S fragments feed P.V directly as packed-half A-fragments (no shuffles).
// ---------------------------------------------------------------------------
#define FSM 136   // smem row stride in halves (128 + 8 pad)
#define FLASH_SMEM (3 * 128 * FSM * 2)   // 104448 bytes

__global__ void __launch_bounds__(256)
flash_h(const __half* __restrict__ qkv, const uint8_t* __restrict__ mask,
        __half* __restrict__ ctx)
{
    const int qblk = 15 - (int)(blockIdx.x >> 4);   // heavy CTAs first
    const int head = blockIdx.x & 15;

    extern __shared__ __half smf[];
    __half* Qs = smf;                  // [128][FSM]
    __half* Ks = Qs + 128 * FSM;
    __half* Vs = Ks + 128 * FSM;

    const int tid  = threadIdx.x;
    const int w    = tid >> 5;
    const int lane = tid & 31;
    const int g    = lane >> 2;
    const int t    = lane & 3;

    const float inv_norm = 0.08838834764831845f;   // 1/sqrt(128)

    // ---- Q block: cp.async (group) ----
    const __half* qsrc = qkv + (size_t)(qblk * 128) * QKV_N + head * 384;
    #pragma unroll
    for (int i = 0; i < 8; i++) {
        int idx = tid + i * 256;
        int r = idx >> 4, sgo = (idx & 15) * 8;
        cp16(Qs + r * FSM + sgo, qsrc + (size_t)r * QKV_N + sgo);
    }
    CP_COMMIT();

    float o[16][4];
    #pragma unroll
    for (int ni = 0; ni < 16; ni++)
        #pragma unroll
        for (int q = 0; q < 4; q++) o[ni][q] = 0.0f;

    float m0 = -1e30f, m1 = -1e30f, l0 = 0.0f, l1 = 0.0f;

    const int row0g = qblk * 128 + w * 16 + g;
    const int row1g = row0g + 8;

    // ldmatrix lane addressing
    const int qa_row = w * 16 + (lane & 15);                 // A frag rows
    const int qa_col = (lane >> 4) << 3;                     // + kk*16
    const int kb_row = ((lane >> 4) << 3) + (lane & 7);      // + np*16
    const int kb_col = ((lane >> 3) & 1) << 3;               // + kk*16
    const int vb_row = (((lane >> 3) & 1) << 3) + (lane & 7);// + kb*16
    const int vb_col = (lane >> 4) << 3;                     // + np*16

    for (int j = 0; j <= qblk; j++) {
        __syncthreads();   // previous tile fully consumed
        const __half* ksrc = qkv + (size_t)(j * 128) * QKV_N + head * 384 + 128;
        const __half* vsrc = ksrc + 128;
        #pragma unroll
        for (int i = 0; i < 8; i++) {
            int idx = tid + i * 256;
            int r = idx >> 4, sgo = (idx & 15) * 8;
            cp16(Ks + r * FSM + sgo, ksrc + (size_t)r * QKV_N + sgo);
        }
        CP_COMMIT();                    // K group
        #pragma unroll
        for (int i = 0; i < 8; i++) {
            int idx = tid + i * 256;
            int r = idx >> 4, sgo = (idx & 15) * 8;
            cp16(Vs + r * FSM + sgo, vsrc + (size_t)r * QKV_N + sgo);
        }
        CP_COMMIT();                    // V group

        CP_WAIT(1);                     // K (and Q on iter 0) arrived
        __syncthreads();

        // ---- S = Q . K^T ----
        float s[16][4];
        #pragma unroll
        for (int ni = 0; ni < 16; ni++)
            #pragma unroll
            for (int q = 0; q < 4; q++) s[ni][q] = 0.0f;

        #pragma unroll
        for (int kk = 0; kk < 8; kk++) {
            uint32_t aq[4];
            ldsm_x4(aq, Qs + (size_t)qa_row * FSM + kk * 16 + qa_col);
            #pragma unroll
            for (int np = 0; np < 8; np++) {
                uint32_t bk[4];
                ldsm_x4(bk, Ks + (size_t)(kb_row + np * 16) * FSM + kk * 16 + kb_col);
                mma_f16(s[2 * np],     aq, bk);
                mma_f16(s[2 * np + 1], aq, bk + 2);
            }
        }

        // ---- scale + user mask + causal ----
        const uint8_t* mr0 = mask + (size_t)row0g * SEQ + j * 128;
        const uint8_t* mr1 = mask + (size_t)row1g * SEQ + j * 128;
        const bool diag = (j == qblk);
        #pragma unroll
        for (int ni = 0; ni < 16; ni++) {
            int c = ni * 8 + 2 * t;
            s[ni][0] *= inv_norm; s[ni][1] *= inv_norm;
            s[ni][2] *= inv_norm; s[ni][3] *= inv_norm;
            unsigned short mm0 = *(const unsigned short*)(mr0 + c);
            unsigned short mm1 = *(const unsigned short*)(mr1 + c);
            if (mm0 & 0x00FF) s[ni][0] = MASK_VAL;
            if (mm0 & 0xFF00) s[ni][1] = MASK_VAL;
            if (mm1 & 0x00FF) s[ni][2] = MASK_VAL;
            if (mm1 & 0xFF00) s[ni][3] = MASK_VAL;
            if (diag) {
                int cg = j * 128 + c;
                if (cg     > row0g) s[ni][0] = -1e30f;
                if (cg + 1 > row0g) s[ni][1] = -1e30f;
                if (cg     > row1g) s[ni][2] = -1e30f;
                if (cg + 1 > row1g) s[ni][3] = -1e30f;
            }
        }

        // ---- online softmax ----
        float mx0 = -1e30f, mx1 = -1e30f;
        #pragma unroll
        for (int ni = 0; ni < 16; ni++) {
            mx0 = fmaxf(mx0, fmaxf(s[ni][0], s[ni][1]));
            mx1 = fmaxf(mx1, fmaxf(s[ni][2], s[ni][3]));
        }
        mx0 = fmaxf(mx0, __shfl_xor_sync(0xFFFFFFFFu, mx0, 1));
        mx0 = fmaxf(mx0, __shfl_xor_sync(0xFFFFFFFFu, mx0, 2));
        mx1 = fmaxf(mx1, __shfl_xor_sync(0xFFFFFFFFu, mx1, 1));
        mx1 = fmaxf(mx1, __shfl_xor_sync(0xFFFFFFFFu, mx1, 2));

        float mn0 = fmaxf(m0, mx0), mn1 = fmaxf(m1, mx1);
        float al0 = __expf(m0 - mn0), al1 = __expf(m1 - mn1);
        m0 = mn0; m1 = mn1;

        float sum0 = 0.0f, sum1 = 0.0f;
        #pragma unroll
        for (int ni = 0; ni < 16; ni++) {
            s[ni][0] = __expf(s[ni][0] - mn0);
            s[ni][1] = __expf(s[ni][1] - mn0);
            s[ni][2] = __expf(s[ni][2] - mn1);
            s[ni][3] = __expf(s[ni][3] - mn1);
            sum0 += s[ni][0] + s[ni][1];
            sum1 += s[ni][2] + s[ni][3];
        }
        sum0 += __shfl_xor_sync(0xFFFFFFFFu, sum0, 1);
        sum0 += __shfl_xor_sync(0xFFFFFFFFu, sum0, 2);
        sum1 += __shfl_xor_sync(0xFFFFFFFFu, sum1, 1);
        sum1 += __shfl_xor_sync(0xFFFFFFFFu, sum1, 2);
        l0 = l0 * al0 + sum0;
        l1 = l1 * al1 + sum1;

        #pragma unroll
        for (int ni = 0; ni < 16; ni++) {
            o[ni][0] *= al0; o[ni][1] *= al0;
            o[ni][2] *= al1; o[ni][3] *= al1;
        }

        CP_WAIT(0);        // V arrived (overlapped with S + softmax)
        __syncthreads();

        // ---- O += P . V  (P packs straight from S fragments) ----
        #pragma unroll
        for (int kb = 0; kb < 8; kb++) {
            uint32_t pa[4];
            pa[0] = pack_h2(s[2 * kb][0],     s[2 * kb][1]);
            pa[1] = pack_h2(s[2 * kb][2],     s[2 * kb][3]);
            pa[2] = pack_h2(s[2 * kb + 1][0], s[2 * kb + 1][1]);
            pa[3] = pack_h2(s[2 * kb + 1][2], s[2 * kb + 1][3]);
            #pragma unroll
            for (int np = 0; np < 8; np++) {
                uint32_t bv[4];
                ldsm_x4_t(bv, Vs + (size_t)(vb_row + kb * 16) * FSM + np * 16 + vb_col);
                mma_f16(o[2 * np],     pa, bv);
                mma_f16(o[2 * np + 1], pa, bv + 2);
            }
        }
    }

    // ---- epilogue: O / l -> ctx (fp16) ----
    const float il0 = 1.0f / l0;
    const float il1 = 1.0f / l1;
    __half* c0 = ctx + (size_t)row0g * HID + head * HDIM;
    __half* c1 = ctx + (size_t)row1g * HID + head * HDIM;
    #pragma unroll
    for (int ni = 0; ni < 16; ni++) {
        int c = ni * 8 + 2 * t;
        *(uint32_t*)(c0 + c) = pack_h2(o[ni][0] * il0, o[ni][1] * il0);
        *(uint32_t*)(c1 + c) = pack_h2(o[ni][2] * il1, o[ni][3] * il1);
    }
}

__global__ void copy_bias(const float* __restrict__ b, float* __restrict__ out)
{
    int i = blockIdx.x * 256 + threadIdx.x;
    if (i < HID) out[i] = b[i];
}

// ============================================================================
extern "C" void kernel_launch(void* const* d_in, const int* in_sizes, int n_in,
                              void* d_out, int out_size)
{
    const float*   hs     = (const float*)d_in[0];   // [2048, 1, 2048]
    const float*   w_qkv  = (const float*)d_in[1];   // [6144, 2048]
    const float*   b_qkv  = (const float*)d_in[2];   // [6144]
    const float*   w_proj = (const float*)d_in[3];   // [2048, 2048]
    const float*   b_proj = (const float*)d_in[4];   // [2048]
    const uint8_t* mask   = (const uint8_t*)d_in[5]; // [1,1,2048,2048] bool

    __half *qkv, *ctx, *phs, *pwqkv, *pwproj;
    cudaGetSymbolAddress((void**)&qkv,    g_qkv);
    cudaGetSymbolAddress((void**)&ctx,    g_ctx);
    cudaGetSymbolAddress((void**)&phs,    g_hs);
    cudaGetSymbolAddress((void**)&pwqkv,  g_wqkv);
    cudaGetSymbolAddress((void**)&pwproj, g_wproj);
    float* out = (float*)d_out;

    static bool attr_set = false;
    if (!attr_set) {
        cudaFuncSetAttribute(flash_h, cudaFuncAttributeMaxDynamicSharedMemorySize, FLASH_SMEM);
        cudaFuncSetAttribute(gemm_h<true>,  cudaFuncAttributeMaxDynamicSharedMemorySize, GEMM_SMEM);
        cudaFuncSetAttribute(gemm_h<false>, cudaFuncAttributeMaxDynamicSharedMemorySize, GEMM_SMEM);
        attr_set = true;
    }

    // 0) convert inputs to fp16
    prep_h<<<(SEQ * HID / 4 + 255) / 256, 256>>>(hs,     phs,    SEQ * HID / 4);
    prep_h<<<(QKV_N * HID / 4 + 255) / 256, 256>>>(w_qkv, pwqkv,  QKV_N * HID / 4);
    prep_h<<<(HID * HID / 4 + 255) / 256, 256>>>(w_proj, pwproj, HID * HID / 4);

    // 1) fused QKV GEMM -> fp16 qkv
    gemm_h<true><<<dim3(QKV_N / 128, SEQ / 128), 256, GEMM_SMEM>>>(
        phs, HID, pwqkv, HID, qkv, QKV_N, b_qkv, HID);

    // 2) fused attention: BMM1 + causal softmax + BMM2 -> fp16 ctx
    flash_h<<<dim3(16 * NHEAD), 256, FLASH_SMEM>>>(qkv, mask, ctx);

    // 3) output projection (fp32 output)
    gemm_h<false><<<dim3(HID / 128, SEQ / 128), 256, GEMM_SMEM>>>(
        ctx, HID, pwproj, HID, out, HID, nullptr, HID);

    // 4) tuple second element: b_proj appended after the [S*H] projection output
    if (out_size >= SEQ * HID + HID) {
        copy_bias<<<(HID + 255) / 256, 256>>>(b_proj, out + (size_t)SEQ * HID);
    }
}

// round 7
// speedup vs baseline: 7.3922x; 1.1788x over previous
#include <cuda_runtime.h>
#include <cuda_fp16.h>
#include <math.h>
#include <stdint.h>

// Problem constants (fixed shapes from reference)
#define SEQ   2048
#define HID   2048
#define NHEAD 16
#define HDIM  128
#define QKV_N (3 * HID)   // 6144
#define MASK_VAL (-10000.0f)

// -------- device scratch (static; no allocations allowed) --------
__device__ __half g_qkv[SEQ * QKV_N];     // [s, 3h] QKV output (fp16)
__device__ __half g_ctx[SEQ * HID];       // [s, h] context (fp16)
__device__ __half g_hs[SEQ * HID];        // fp16 hidden_states
__device__ __half g_wqkv[QKV_N * HID];    // fp16 w_qkv
__device__ __half g_wproj[HID * HID];     // fp16 w_proj

// ---------------------------------------------------------------------------
// helpers
// ---------------------------------------------------------------------------
__device__ __forceinline__ uint32_t pack_h2(float lo, float hi) {
    __half2 h = __floats2half2_rn(lo, hi);
    return *reinterpret_cast<uint32_t*>(&h);
}

__device__ __forceinline__ void mma_f16(float* d, const uint32_t* a, const uint32_t* b) {
    asm volatile(
        "mma.sync.aligned.m16n8k16.row.col.f32.f16.f16.f32 "
        "{%0,%1,%2,%3}, {%4,%5,%6,%7}, {%8,%9}, {%0,%1,%2,%3};"
        : "+f"(d[0]), "+f"(d[1]), "+f"(d[2]), "+f"(d[3])
        : "r"(a[0]), "r"(a[1]), "r"(a[2]), "r"(a[3]), "r"(b[0]), "r"(b[1]));
}

__device__ __forceinline__ void ldsm_x4(uint32_t* r, const void* p) {
    uint32_t a = (uint32_t)__cvta_generic_to_shared(p);
    asm volatile("ldmatrix.sync.aligned.m8n8.x4.shared.b16 {%0,%1,%2,%3}, [%4];"
        : "=r"(r[0]), "=r"(r[1]), "=r"(r[2]), "=r"(r[3]) : "r"(a));
}

__device__ __forceinline__ void ldsm_x4_t(uint32_t* r, const void* p) {
    uint32_t a = (uint32_t)__cvta_generic_to_shared(p);
    asm volatile("ldmatrix.sync.aligned.m8n8.x4.trans.shared.b16 {%0,%1,%2,%3}, [%4];"
        : "=r"(r[0]), "=r"(r[1]), "=r"(r[2]), "=r"(r[3]) : "r"(a));
}

__device__ __forceinline__ void cp16(void* dst_smem, const void* src) {
    uint32_t d = (uint32_t)__cvta_generic_to_shared(dst_smem);
    asm volatile("cp.async.cg.shared.global [%0], [%1], 16;" :: "r"(d), "l"(src));
}
#define CP_COMMIT() asm volatile("cp.async.commit_group;" ::: "memory")
#define CP_WAIT(N)  asm volatile("cp.async.wait_group %0;" :: "n"(N) : "memory")

// ---------------------------------------------------------------------------
// fp32 -> fp16 conversion (4 elems/thread)
// ---------------------------------------------------------------------------
__global__ void __launch_bounds__(256)
prep_h(const float* __restrict__ src, __half* __restrict__ dst, int n4)
{
    int i = blockIdx.x * 256 + threadIdx.x;
    if (i < n4) {
        float4 v = ((const float4*)src)[i];
        uint2 u = make_uint2(pack_h2(v.x, v.y), pack_h2(v.z, v.w));
        ((uint2*)dst)[i] = u;
    }
}

// ---------------------------------------------------------------------------
// fp16 mma.sync GEMM: C = A * B^T + bias.
//   A[M,K] fp16 row-major, B[N,K] fp16 row-major.
//   CTA 128x128, BK=64, 3-stage cp.async, 8 warps (2M x 4N), warp 64x32.
//   4 unrolled k-steps per barrier window -> deep MMA/LDSM overlap.
// ---------------------------------------------------------------------------
#define HSM 72               // smem row stride in halves (64 data + 8 pad)
#define GSTG 3
#define GEMM_SMEM (GSTG * 2 * 128 * HSM * 2)   // 110592 bytes

template<bool OUT_HALF>
__global__ void __launch_bounds__(256, 2)
gemm_h(const __half* __restrict__ A, int lda,
       const __half* __restrict__ B, int ldb,
       void* __restrict__ Cv, int ldc,
       const float* __restrict__ bias, int K)
{
    extern __shared__ __half smh[];
    __half* As = smh;                          // [GSTG][128*HSM]
    __half* Bs = smh + GSTG * 128 * HSM;

    const int tid = threadIdx.x;
    const int wid = tid >> 5;
    const int lane = tid & 31;
    const int t = lane & 3;
    const int g = lane >> 2;
    const int wm = wid & 1;
    const int wn = wid >> 1;

    A += (size_t)(blockIdx.y * 128) * lda;
    B += (size_t)(blockIdx.x * 128) * ldb;

    float acc[4][4][4];
    #pragma unroll
    for (int mi = 0; mi < 4; mi++)
        #pragma unroll
        for (int ni = 0; ni < 4; ni++)
            #pragma unroll
            for (int q = 0; q < 4; q++) acc[mi][ni][q] = 0.0f;

    const int nch = K >> 6;   // K / 64

    // one stage: 128 rows x 64 halves (128B) per matrix = 8 segs/row
    auto issue = [&](int st, int k0) {
        __half* as = As + st * 128 * HSM;
        __half* bs = Bs + st * 128 * HSM;
        #pragma unroll
        for (int i = 0; i < 4; i++) {
            int idx = tid + i * 256;     // 0..1023
            int r = idx >> 3;            // 0..127
            int sgo = (idx & 7) * 8;     // halves
            cp16(as + r * HSM + sgo, A + (size_t)r * lda + k0 + sgo);
            cp16(bs + r * HSM + sgo, B + (size_t)r * ldb + k0 + sgo);
        }
        CP_COMMIT();
    };

    issue(0, 0);
    if (nch > 1) issue(1, 64);

    // ldmatrix lane addressing (constant per thread)
    const int a_row = wm * 64 + (lane & 15);                       // + mi*16
    const int a_col = (lane >> 4) << 3;                            // + ks*16
    const int b_row = wn * 32 + ((lane >> 4) << 3) + (lane & 7);   // + np*16
    const int b_col = ((lane >> 3) & 1) << 3;                      // + ks*16

    for (int c = 0; c < nch; c++) {
        if (c + 1 < nch) { CP_WAIT(1); } else { CP_WAIT(0); }
        __syncthreads();
        if (c + 2 < nch) issue((c + 2) % GSTG, (c + 2) * 64);

        const __half* as = As + (c % GSTG) * 128 * HSM;
        const __half* bs = Bs + (c % GSTG) * 128 * HSM;
        #pragma unroll
        for (int ks = 0; ks < 4; ks++) {
            uint32_t af[4][4], bf[2][4];
            #pragma unroll
            for (int mi = 0; mi < 4; mi++)
                ldsm_x4(af[mi], as + (size_t)(a_row + mi * 16) * HSM + ks * 16 + a_col);
            #pragma unroll
            for (int np = 0; np < 2; np++)
                ldsm_x4(bf[np], bs + (size_t)(b_row + np * 16) * HSM + ks * 16 + b_col);
            #pragma unroll
            for (int mi = 0; mi < 4; mi++)
                #pragma unroll
                for (int ni = 0; ni < 4; ni++)
                    mma_f16(acc[mi][ni], af[mi], &bf[ni >> 1][(ni & 1) * 2]);
        }
    }

    // epilogue
    #pragma unroll
    for (int mi = 0; mi < 4; mi++) {
        const int r0 = blockIdx.y * 128 + wm * 64 + mi * 16 + g;
        #pragma unroll
        for (int ni = 0; ni < 4; ni++) {
            const int col = blockIdx.x * 128 + wn * 32 + ni * 8 + t * 2;
            float bv0 = 0.0f, bv1 = 0.0f;
            if (bias != nullptr) { bv0 = bias[col]; bv1 = bias[col + 1]; }
            float r00 = acc[mi][ni][0] + bv0;
            float r01 = acc[mi][ni][1] + bv1;
            float r10 = acc[mi][ni][2] + bv0;
            float r11 = acc[mi][ni][3] + bv1;
            if (OUT_HALF) {
                __half* C = (__half*)Cv;
                *(uint32_t*)(C + (size_t)r0 * ldc + col)       = pack_h2(r00, r01);
                *(uint32_t*)(C + (size_t)(r0 + 8) * ldc + col) = pack_h2(r10, r11);
            } else {
                float* C = (float*)Cv;
                *(float2*)(C + (size_t)r0 * ldc + col)       = make_float2(r00, r01);
                *(float2*)(C + (size_t)(r0 + 8) * ldc + col) = make_float2(r10, r11);
            }
        }
    }
}

// ---------------------------------------------------------------------------
// Fused fp16 flash attention (BMM1 + causal softmax + BMM2).
//   CTA = (q-block 128 rows, head). 8 warps x 16 rows. Online softmax.
//   S fragments feed P.V directly as packed-half A-fragments (no shuffles).
// ---------------------------------------------------------------------------
#define FSM 136   // smem row stride in halves (128 + 8 pad)
#define FLASH_SMEM (3 * 128 * FSM * 2)   // 104448 bytes

__global__ void __launch_bounds__(256)
flash_h(const __half* __restrict__ qkv, const uint8_t* __restrict__ mask,
        __half* __restrict__ ctx)
{
    const int qblk = 15 - (int)(blockIdx.x >> 4);   // heavy CTAs first
    const int head = blockIdx.x & 15;

    extern __shared__ __half smf[];
    __half* Qs = smf;                  // [128][FSM]
    __half* Ks = Qs + 128 * FSM;
    __half* Vs = Ks + 128 * FSM;

    const int tid  = threadIdx.x;
    const int w    = tid >> 5;
    const int lane = tid & 31;
    const int g    = lane >> 2;
    const int t    = lane & 3;

    const float inv_norm = 0.08838834764831845f;   // 1/sqrt(128)

    // ---- Q block: cp.async (group) ----
    const __half* qsrc = qkv + (size_t)(qblk * 128) * QKV_N + head * 384;
    #pragma unroll
    for (int i = 0; i < 8; i++) {
        int idx = tid + i * 256;
        int r = idx >> 4, sgo = (idx & 15) * 8;
        cp16(Qs + r * FSM + sgo, qsrc + (size_t)r * QKV_N + sgo);
    }
    CP_COMMIT();

    float o[16][4];
    #pragma unroll
    for (int ni = 0; ni < 16; ni++)
        #pragma unroll
        for (int q = 0; q < 4; q++) o[ni][q] = 0.0f;

    float m0 = -1e30f, m1 = -1e30f, l0 = 0.0f, l1 = 0.0f;

    const int row0g = qblk * 128 + w * 16 + g;
    const int row1g = row0g + 8;

    // ldmatrix lane addressing
    const int qa_row = w * 16 + (lane & 15);                 // A frag rows
    const int qa_col = (lane >> 4) << 3;                     // + kk*16
    const int kb_row = ((lane >> 4) << 3) + (lane & 7);      // + np*16
    const int kb_col = ((lane >> 3) & 1) << 3;               // + kk*16
    const int vb_row = (((lane >> 3) & 1) << 3) + (lane & 7);// + kb*16
    const int vb_col = (lane >> 4) << 3;                     // + np*16

    for (int j = 0; j <= qblk; j++) {
        __syncthreads();   // previous tile fully consumed
        const __half* ksrc = qkv + (size_t)(j * 128) * QKV_N + head * 384 + 128;
        const __half* vsrc = ksrc + 128;
        #pragma unroll
        for (int i = 0; i < 8; i++) {
            int idx = tid + i * 256;
            int r = idx >> 4, sgo = (idx & 15) * 8;
            cp16(Ks + r * FSM + sgo, ksrc + (size_t)r * QKV_N + sgo);
        }
        CP_COMMIT();                    // K group
        #pragma unroll
        for (int i = 0; i < 8; i++) {
            int idx = tid + i * 256;
            int r = idx >> 4, sgo = (idx & 15) * 8;
            cp16(Vs + r * FSM + sgo, vsrc + (size_t)r * QKV_N + sgo);
        }
        CP_COMMIT();                    // V group

        CP_WAIT(1);                     // K (and Q on iter 0) arrived
        __syncthreads();

        // ---- S = Q . K^T ----
        float s[16][4];
        #pragma unroll
        for (int ni = 0; ni < 16; ni++)
            #pragma unroll
            for (int q = 0; q < 4; q++) s[ni][q] = 0.0f;

        #pragma unroll
        for (int kk = 0; kk < 8; kk++) {
            uint32_t aq[4];
            ldsm_x4(aq, Qs + (size_t)qa_row * FSM + kk * 16 + qa_col);
            #pragma unroll
            for (int np = 0; np < 8; np++) {
                uint32_t bk[4];
                ldsm_x4(bk, Ks + (size_t)(kb_row + np * 16) * FSM + kk * 16 + kb_col);
                mma_f16(s[2 * np],     aq, bk);
                mma_f16(s[2 * np + 1], aq, bk + 2);
            }
        }

        // ---- scale + user mask + causal ----
        const uint8_t* mr0 = mask + (size_t)row0g * SEQ + j * 128;
        const uint8_t* mr1 = mask + (size_t)row1g * SEQ + j * 128;
        const bool diag = (j == qblk);
        #pragma unroll
        for (int ni = 0; ni < 16; ni++) {
            int c = ni * 8 + 2 * t;
            s[ni][0] *= inv_norm; s[ni][1] *= inv_norm;
            s[ni][2] *= inv_norm; s[ni][3] *= inv_norm;
            unsigned short mm0 = *(const unsigned short*)(mr0 + c);
            unsigned short mm1 = *(const unsigned short*)(mr1 + c);
            if (mm0 & 0x00FF) s[ni][0] = MASK_VAL;
            if (mm0 & 0xFF00) s[ni][1] = MASK_VAL;
            if (mm1 & 0x00FF) s[ni][2] = MASK_VAL;
            if (mm1 & 0xFF00) s[ni][3] = MASK_VAL;
            if (diag) {
                int cg = j * 128 + c;
                if (cg     > row0g) s[ni][0] = -1e30f;
                if (cg + 1 > row0g) s[ni][1] = -1e30f;
                if (cg     > row1g) s[ni][2] = -1e30f;
                if (cg + 1 > row1g) s[ni][3] = -1e30f;
            }
        }

        // ---- online softmax ----
        float mx0 = -1e30f, mx1 = -1e30f;
        #pragma unroll
        for (int ni = 0; ni < 16; ni++) {
            mx0 = fmaxf(mx0, fmaxf(s[ni][0], s[ni][1]));
            mx1 = fmaxf(mx1, fmaxf(s[ni][2], s[ni][3]));
        }
        mx0 = fmaxf(mx0, __shfl_xor_sync(0xFFFFFFFFu, mx0, 1));
        mx0 = fmaxf(mx0, __shfl_xor_sync(0xFFFFFFFFu, mx0, 2));
        mx1 = fmaxf(mx1, __shfl_xor_sync(0xFFFFFFFFu, mx1, 1));
        mx1 = fmaxf(mx1, __shfl_xor_sync(0xFFFFFFFFu, mx1, 2));

        float mn0 = fmaxf(m0, mx0), mn1 = fmaxf(m1, mx1);
        float al0 = __expf(m0 - mn0), al1 = __expf(m1 - mn1);
        m0 = mn0; m1 = mn1;

        float sum0 = 0.0f, sum1 = 0.0f;
        #pragma unroll
        for (int ni = 0; ni < 16; ni++) {
            s[ni][0] = __expf(s[ni][0] - mn0);
            s[ni][1] = __expf(s[ni][1] - mn0);
            s[ni][2] = __expf(s[ni][2] - mn1);
            s[ni][3] = __expf(s[ni][3] - mn1);
            sum0 += s[ni][0] + s[ni][1];
            sum1 += s[ni][2] + s[ni][3];
        }
        sum0 += __shfl_xor_sync(0xFFFFFFFFu, sum0, 1);
        sum0 += __shfl_xor_sync(0xFFFFFFFFu, sum0, 2);
        sum1 += __shfl_xor_sync(0xFFFFFFFFu, sum1, 1);
        sum1 += __shfl_xor_sync(0xFFFFFFFFu, sum1, 2);
        l0 = l0 * al0 + sum0;
        l1 = l1 * al1 + sum1;

        #pragma unroll
        for (int ni = 0; ni < 16; ni++) {
            o[ni][0] *= al0; o[ni][1] *= al0;
            o[ni][2] *= al1; o[ni][3] *= al1;
        }

        CP_WAIT(0);        // V arrived (overlapped with S + softmax)
        __syncthreads();

        // ---- O += P . V  (P packs straight from S fragments) ----
        #pragma unroll
        for (int kb = 0; kb < 8; kb++) {
            uint32_t pa[4];
            pa[0] = pack_h2(s[2 * kb][0],     s[2 * kb][1]);
            pa[1] = pack_h2(s[2 * kb][2],     s[2 * kb][3]);
            pa[2] = pack_h2(s[2 * kb + 1][0], s[2 * kb + 1][1]);
            pa[3] = pack_h2(s[2 * kb + 1][2], s[2 * kb + 1][3]);
            #pragma unroll
            for (int np = 0; np < 8; np++) {
                uint32_t bv[4];
                ldsm_x4_t(bv, Vs + (size_t)(vb_row + kb * 16) * FSM + np * 16 + vb_col);
                mma_f16(o[2 * np],     pa, bv);
                mma_f16(o[2 * np + 1], pa, bv + 2);
            }
        }
    }

    // ---- epilogue: O / l -> ctx (fp16) ----
    const float il0 = 1.0f / l0;
    const float il1 = 1.0f / l1;
    __half* c0 = ctx + (size_t)row0g * HID + head * HDIM;
    __half* c1 = ctx + (size_t)row1g * HID + head * HDIM;
    #pragma unroll
    for (int ni = 0; ni < 16; ni++) {
        int c = ni * 8 + 2 * t;
        *(uint32_t*)(c0 + c) = pack_h2(o[ni][0] * il0, o[ni][1] * il0);
        *(uint32_t*)(c1 + c) = pack_h2(o[ni][2] * il1, o[ni][3] * il1);
    }
}

__global__ void copy_bias(const float* __restrict__ b, float* __restrict__ out)
{
    int i = blockIdx.x * 256 + threadIdx.x;
    if (i < HID) out[i] = b[i];
}

// ============================================================================
extern "C" void kernel_launch(void* const* d_in, const int* in_sizes, int n_in,
                              void* d_out, int out_size)
{
    const float*   hs     = (const float*)d_in[0];   // [2048, 1, 2048]
    const float*   w_qkv  = (const float*)d_in[1];   // [6144, 2048]
    const float*   b_qkv  = (const float*)d_in[2];   // [6144]
    const float*   w_proj = (const float*)d_in[3];   // [2048, 2048]
    const float*   b_proj = (const float*)d_in[4];   // [2048]
    const uint8_t* mask   = (const uint8_t*)d_in[5]; // [1,1,2048,2048] bool

    __half *qkv, *ctx, *phs, *pwqkv, *pwproj;
    cudaGetSymbolAddress((void**)&qkv,    g_qkv);
    cudaGetSymbolAddress((void**)&ctx,    g_ctx);
    cudaGetSymbolAddress((void**)&phs,    g_hs);
    cudaGetSymbolAddress((void**)&pwqkv,  g_wqkv);
    cudaGetSymbolAddress((void**)&pwproj, g_wproj);
    float* out = (float*)d_out;

    static bool attr_set = false;
    if (!attr_set) {
        cudaFuncSetAttribute(flash_h, cudaFuncAttributeMaxDynamicSharedMemorySize, FLASH_SMEM);
        cudaFuncSetAttribute(gemm_h<true>,  cudaFuncAttributeMaxDynamicSharedMemorySize, GEMM_SMEM);
        cudaFuncSetAttribute(gemm_h<false>, cudaFuncAttributeMaxDynamicSharedMemorySize, GEMM_SMEM);
        attr_set = true;
    }

    // 0) convert inputs to fp16
    prep_h<<<(SEQ * HID / 4 + 255) / 256, 256>>>(hs,     phs,    SEQ * HID / 4);
    prep_h<<<(QKV_N * HID / 4 + 255) / 256, 256>>>(w_qkv, pwqkv,  QKV_N * HID / 4);
    prep_h<<<(HID * HID / 4 + 255) / 256, 256>>>(w_proj, pwproj, HID * HID / 4);

    // 1) fused QKV GEMM -> fp16 qkv
    gemm_h<true><<<dim3(QKV_N / 128, SEQ / 128), 256, GEMM_SMEM>>>(
        phs, HID, pwqkv, HID, qkv, QKV_N, b_qkv, HID);

    // 2) fused attention: BMM1 + causal softmax + BMM2 -> fp16 ctx
    flash_h<<<dim3(16 * NHEAD), 256, FLASH_SMEM>>>(qkv, mask, ctx);

    // 3) output projection (fp32 output)
    gemm_h<false><<<dim3(HID / 128, SEQ / 128), 256, GEMM_SMEM>>>(
        ctx, HID, pwproj, HID, out, HID, nullptr, HID);

    // 4) tuple second element: b_proj appended after the [S*H] projection output
    if (out_size >= SEQ * HID + HID) {
        copy_bias<<<(HID + 255) / 256, 256>>>(b_proj, out + (size_t)SEQ * HID);
    }
}